// round 1
// baseline (speedup 1.0000x reference)
#include <cuda_runtime.h>
#include <math.h>

#define BB 2
#define SEQ 2048
#define HID 2048
#define NH 16
#define HD 128
#define MROWS (BB*SEQ)   // 4096

// Scratch (allocation-free rule: __device__ globals)
__device__ float g_q[(size_t)MROWS * HID];
__device__ float g_k[(size_t)MROWS * HID];
__device__ float g_v[(size_t)MROWS * HID];
__device__ float g_att[(size_t)MROWS * HID];

// ---------------------------------------------------------------------------
// SGEMM (NT): C[m][n] = sum_k A[m][k] * W[n][k]
// BM=BN=128, BK=16, 256 threads, 8x8 microtile
// ---------------------------------------------------------------------------
__global__ __launch_bounds__(256) void sgemm_nt(const float* __restrict__ A,
                                                const float* __restrict__ W,
                                                float* __restrict__ C,
                                                int Md, int Nd, int Kd)
{
    const int BM = 128, BN = 128, BK = 16;
    __shared__ float As[BK][BM];
    __shared__ float Bs[BK][BN];

    const int bm = blockIdx.y * BM;
    const int bn = blockIdx.x * BN;
    const int tid = threadIdx.x;
    const int tr = tid >> 4;          // 0..15 -> rows tr*8..tr*8+7
    const int tc = tid & 15;          // 0..15 -> cols tc*8..tc*8+7
    const int lr = tid >> 2;          // 0..63
    const int lc = (tid & 3) << 2;    // 0,4,8,12

    float acc[8][8];
#pragma unroll
    for (int i = 0; i < 8; i++)
#pragma unroll
        for (int j = 0; j < 8; j++) acc[i][j] = 0.f;

    for (int k0 = 0; k0 < Kd; k0 += BK) {
#pragma unroll
        for (int p = 0; p < 2; p++) {
            int row = lr + p * 64;
            float4 a = *(const float4*)(A + (size_t)(bm + row) * Kd + k0 + lc);
            As[lc + 0][row] = a.x; As[lc + 1][row] = a.y;
            As[lc + 2][row] = a.z; As[lc + 3][row] = a.w;
            float4 w = *(const float4*)(W + (size_t)(bn + row) * Kd + k0 + lc);
            Bs[lc + 0][row] = w.x; Bs[lc + 1][row] = w.y;
            Bs[lc + 2][row] = w.z; Bs[lc + 3][row] = w.w;
        }
        __syncthreads();

#pragma unroll
        for (int kk = 0; kk < BK; kk++) {
            float a[8], b[8];
            *(float4*)&a[0] = *(const float4*)&As[kk][tr * 8];
            *(float4*)&a[4] = *(const float4*)&As[kk][tr * 8 + 4];
            *(float4*)&b[0] = *(const float4*)&Bs[kk][tc * 8];
            *(float4*)&b[4] = *(const float4*)&Bs[kk][tc * 8 + 4];
#pragma unroll
            for (int i = 0; i < 8; i++)
#pragma unroll
                for (int j = 0; j < 8; j++)
                    acc[i][j] = fmaf(a[i], b[j], acc[i][j]);
        }
        __syncthreads();
    }

#pragma unroll
    for (int i = 0; i < 8; i++) {
        float* cp = C + (size_t)(bm + tr * 8 + i) * Nd + bn + tc * 8;
        *(float4*)cp       = make_float4(acc[i][0], acc[i][1], acc[i][2], acc[i][3]);
        *(float4*)(cp + 4) = make_float4(acc[i][4], acc[i][5], acc[i][6], acc[i][7]);
    }
}

// ---------------------------------------------------------------------------
// RoPE in-place on g_q, g_k.  layout [B, S, NH, HD] flattened as [B*S, HID]
// thread handles one (b, s, h, d) with d in [0,64): rotates pair (d, d+64)
// ---------------------------------------------------------------------------
__global__ void rope_kernel()
{
    unsigned idx = blockIdx.x * blockDim.x + threadIdx.x;  // 2^22 total
    int d = idx & 63;
    int h = (idx >> 6) & 15;
    int s = (idx >> 10) & 2047;
    int b = idx >> 21;
    if (b >= BB) return;
    size_t base = ((size_t)(b * SEQ + s)) * HID + h * HD;

    float inv = expf(-logf(10000.f) * (float)d * (1.f / 64.f));
    float ang = (float)s * inv;
    float c = cosf(ang), sn = sinf(ang);

    float q1 = g_q[base + d], q2 = g_q[base + d + 64];
    g_q[base + d]      = q1 * c - q2 * sn;
    g_q[base + d + 64] = q2 * c + q1 * sn;

    float k1 = g_k[base + d], k2 = g_k[base + d + 64];
    g_k[base + d]      = k1 * c - k2 * sn;
    g_k[base + d + 64] = k2 * c + k1 * sn;
}

// ---------------------------------------------------------------------------
// Flash attention: per block = (q-tile of 64 rows, one (b,h))
// smem: Qs[64][128], Kt[128][64] (transposed), Vs[64][128], Ps[64][64]
// 256 threads; scores microtile 4x4 (tr rows / tc cols); PV microtile 4x8
// ---------------------------------------------------------------------------
#define ATT_SMEM_FLOATS (64*128 + 128*64 + 64*128 + 64*64)
#define ATT_SMEM_BYTES  (ATT_SMEM_FLOATS * 4)

__global__ __launch_bounds__(256, 2) void attn_kernel()
{
    extern __shared__ float sh[];
    float* Qs = sh;                  // [64][128]
    float* Kt = Qs + 64 * 128;       // [128][64]  (Kt[d][j])
    float* Vs = Kt + 128 * 64;       // [64][128]
    float* Ps = Vs + 64 * 128;       // [64][64]

    const int qt = blockIdx.x;       // 0..31
    const int bh = blockIdx.y;       // 0..31
    const int b = bh >> 4, h = bh & 15;
    const int tid = threadIdx.x;
    const int tr = tid >> 4;         // 0..15 -> q rows tr*4..+3
    const int tc = tid & 15;         // 0..15 -> k cols tc*4..+3 / out cols tc*8..+7

    const float scale = 0.08838834764831844f;  // 1/sqrt(128)

    const float* Qg = g_q + ((size_t)b * SEQ + qt * 64) * HID + h * HD;
    const float* Kg = g_k + ((size_t)b * SEQ) * HID + h * HD;
    const float* Vg = g_v + ((size_t)b * SEQ) * HID + h * HD;

    // load Q tile (scaled)
#pragma unroll
    for (int t = 0; t < 8; t++) {
        int f = tid + 256 * t;           // float4 index
        int row = f >> 5;
        int c4 = (f & 31) << 2;
        float4 q = *(const float4*)(Qg + (size_t)row * HID + c4);
        q.x *= scale; q.y *= scale; q.z *= scale; q.w *= scale;
        *(float4*)&Qs[row * 128 + c4] = q;
    }

    float m_[4], l_[4], o_[4][8];
#pragma unroll
    for (int i = 0; i < 4; i++) {
        m_[i] = -INFINITY; l_[i] = 0.f;
#pragma unroll
        for (int dd = 0; dd < 8; dd++) o_[i][dd] = 0.f;
    }

    for (int kt = 0; kt < SEQ / 64; kt++) {
        const float* Kp = Kg + (size_t)kt * 64 * HID;
        const float* Vp = Vg + (size_t)kt * 64 * HID;
        // load K (transposed) and V tiles
#pragma unroll
        for (int t = 0; t < 8; t++) {
            int f = tid + 256 * t;
            int row = f >> 5;
            int c4 = (f & 31) << 2;
            float4 kv = *(const float4*)(Kp + (size_t)row * HID + c4);
            Kt[(c4 + 0) * 64 + row] = kv.x;
            Kt[(c4 + 1) * 64 + row] = kv.y;
            Kt[(c4 + 2) * 64 + row] = kv.z;
            Kt[(c4 + 3) * 64 + row] = kv.w;
            float4 vv = *(const float4*)(Vp + (size_t)row * HID + c4);
            *(float4*)&Vs[row * 128 + c4] = vv;
        }
        __syncthreads();   // also covers initial Qs visibility

        // scores S = Q Kt  (64x64), microtile 4x4
        float sacc[4][4];
#pragma unroll
        for (int i = 0; i < 4; i++)
#pragma unroll
            for (int j = 0; j < 4; j++) sacc[i][j] = 0.f;

#pragma unroll 4
        for (int d0 = 0; d0 < 128; d0 += 4) {
            float q[4][4], k[4][4];
#pragma unroll
            for (int i = 0; i < 4; i++)
                *(float4*)q[i] = *(const float4*)&Qs[(tr * 4 + i) * 128 + d0];
#pragma unroll
            for (int dd = 0; dd < 4; dd++)
                *(float4*)k[dd] = *(const float4*)&Kt[(d0 + dd) * 64 + tc * 4];
#pragma unroll
            for (int dd = 0; dd < 4; dd++)
#pragma unroll
                for (int i = 0; i < 4; i++)
#pragma unroll
                    for (int j = 0; j < 4; j++)
                        sacc[i][j] = fmaf(q[i][dd], k[dd][j], sacc[i][j]);
        }

        // online softmax (row groups = 16 lanes sharing tr)
#pragma unroll
        for (int i = 0; i < 4; i++) {
            float tm = fmaxf(fmaxf(sacc[i][0], sacc[i][1]),
                             fmaxf(sacc[i][2], sacc[i][3]));
            tm = fmaxf(tm, __shfl_xor_sync(0xffffffffu, tm, 1));
            tm = fmaxf(tm, __shfl_xor_sync(0xffffffffu, tm, 2));
            tm = fmaxf(tm, __shfl_xor_sync(0xffffffffu, tm, 4));
            tm = fmaxf(tm, __shfl_xor_sync(0xffffffffu, tm, 8));
            float mn = fmaxf(m_[i], tm);
            float corr = expf(m_[i] - mn);
            float rs = 0.f;
#pragma unroll
            for (int j = 0; j < 4; j++) {
                float p = expf(sacc[i][j] - mn);
                sacc[i][j] = p;
                rs += p;
            }
            rs += __shfl_xor_sync(0xffffffffu, rs, 1);
            rs += __shfl_xor_sync(0xffffffffu, rs, 2);
            rs += __shfl_xor_sync(0xffffffffu, rs, 4);
            rs += __shfl_xor_sync(0xffffffffu, rs, 8);
            l_[i] = l_[i] * corr + rs;
            m_[i] = mn;
#pragma unroll
            for (int dd = 0; dd < 8; dd++) o_[i][dd] *= corr;
            *(float4*)&Ps[(tr * 4 + i) * 64 + tc * 4] =
                make_float4(sacc[i][0], sacc[i][1], sacc[i][2], sacc[i][3]);
        }
        __syncthreads();

        // O += P V   (64x128), microtile 4x8
#pragma unroll 4
        for (int j0 = 0; j0 < 64; j0 += 4) {
            float p[4][4], v[4][8];
#pragma unroll
            for (int i = 0; i < 4; i++)
                *(float4*)p[i] = *(const float4*)&Ps[(tr * 4 + i) * 64 + j0];
#pragma unroll
            for (int jj = 0; jj < 4; jj++) {
                *(float4*)&v[jj][0] = *(const float4*)&Vs[(j0 + jj) * 128 + tc * 8];
                *(float4*)&v[jj][4] = *(const float4*)&Vs[(j0 + jj) * 128 + tc * 8 + 4];
            }
#pragma unroll
            for (int jj = 0; jj < 4; jj++)
#pragma unroll
                for (int i = 0; i < 4; i++)
#pragma unroll
                    for (int dd = 0; dd < 8; dd++)
                        o_[i][dd] = fmaf(p[i][jj], v[jj][dd], o_[i][dd]);
        }
        __syncthreads();
    }

    // epilogue: normalize + store
    float* Og = g_att + ((size_t)b * SEQ + qt * 64) * HID + h * HD;
#pragma unroll
    for (int i = 0; i < 4; i++) {
        float inv = 1.f / l_[i];
        float* op = Og + (size_t)(tr * 4 + i) * HID + tc * 8;
        *(float4*)op = make_float4(o_[i][0] * inv, o_[i][1] * inv,
                                   o_[i][2] * inv, o_[i][3] * inv);
        *(float4*)(op + 4) = make_float4(o_[i][4] * inv, o_[i][5] * inv,
                                         o_[i][6] * inv, o_[i][7] * inv);
    }
}

// ---------------------------------------------------------------------------
extern "C" void kernel_launch(void* const* d_in, const int* in_sizes, int n_in,
                              void* d_out, int out_size)
{
    const float* x  = (const float*)d_in[0];
    const float* Wq = (const float*)d_in[1];
    const float* Wk = (const float*)d_in[2];
    const float* Wv = (const float*)d_in[3];
    const float* Wo = (const float*)d_in[4];
    float* out = (float*)d_out;

    float *q, *k, *v, *att;
    cudaGetSymbolAddress((void**)&q,   g_q);
    cudaGetSymbolAddress((void**)&k,   g_k);
    cudaGetSymbolAddress((void**)&v,   g_v);
    cudaGetSymbolAddress((void**)&att, g_att);

    dim3 gemm_grid(HID / 128, MROWS / 128);  // (16, 32)

    sgemm_nt<<<gemm_grid, 256>>>(x, Wq, q, MROWS, HID, HID);
    sgemm_nt<<<gemm_grid, 256>>>(x, Wk, k, MROWS, HID, HID);
    sgemm_nt<<<gemm_grid, 256>>>(x, Wv, v, MROWS, HID, HID);

    rope_kernel<<<(1 << 22) / 256, 256>>>();

    cudaFuncSetAttribute(attn_kernel,
                         cudaFuncAttributeMaxDynamicSharedMemorySize,
                         ATT_SMEM_BYTES);
    attn_kernel<<<dim3(SEQ / 64, BB * NH), 256, ATT_SMEM_BYTES>>>();

    sgemm_nt<<<gemm_grid, 256>>>(att, Wo, out, MROWS, HID, HID);
}

// round 3
// speedup vs baseline: 1.4672x; 1.4672x over previous
#include <cuda_runtime.h>
#include <cuda_bf16.h>
#include <math.h>
#include <stdint.h>

#define BB 2
#define SEQ 2048
#define HID 2048
#define NH 16
#define HD 128
#define MROWS (BB*SEQ)   // 4096

// ---------------------------------------------------------------------------
// scratch (allocation-free rule: __device__ globals)
// ---------------------------------------------------------------------------
__device__ float g_q[(size_t)MROWS * HID];
__device__ float g_k[(size_t)MROWS * HID];
__device__ float g_v[(size_t)MROWS * HID];
__device__ float g_att[(size_t)MROWS * HID];

__device__ __nv_bfloat16 g_xhi[(size_t)MROWS * HID];
__device__ __nv_bfloat16 g_xlo[(size_t)MROWS * HID];
__device__ __nv_bfloat16 g_ahi[(size_t)MROWS * HID];
__device__ __nv_bfloat16 g_alo[(size_t)MROWS * HID];
__device__ __nv_bfloat16 g_whi[4][(size_t)HID * HID];
__device__ __nv_bfloat16 g_wlo[4][(size_t)HID * HID];

__device__ __forceinline__ uint32_t smem_u32(const void* p) {
    uint32_t a;
    asm("{ .reg .u64 t; cvta.to.shared.u64 t, %1; cvt.u32.u64 %0, t; }"
        : "=r"(a) : "l"(p));
    return a;
}

#define CP16(sm, gp) \
    asm volatile("cp.async.cg.shared.global [%0], [%1], 16;" \
                 :: "r"(sm), "l"(gp) : "memory")
#define CP_COMMIT() asm volatile("cp.async.commit_group;" ::: "memory")
#define CP_WAIT1()  asm volatile("cp.async.wait_group 1;" ::: "memory")

#define LDSM4(r0,r1,r2,r3, addr) \
    asm volatile("ldmatrix.sync.aligned.m8n8.x4.shared.b16 {%0,%1,%2,%3}, [%4];" \
                 : "=r"(r0),"=r"(r1),"=r"(r2),"=r"(r3) : "r"(addr))
#define LDSM2(r0,r1, addr) \
    asm volatile("ldmatrix.sync.aligned.m8n8.x2.shared.b16 {%0,%1}, [%2];" \
                 : "=r"(r0),"=r"(r1) : "r"(addr))

#define MMA16816(c, a, b) \
    asm volatile("mma.sync.aligned.m16n8k16.row.col.f32.bf16.bf16.f32 " \
                 "{%0,%1,%2,%3},{%4,%5,%6,%7},{%8,%9},{%0,%1,%2,%3};" \
                 : "+f"((c)[0]),"+f"((c)[1]),"+f"((c)[2]),"+f"((c)[3]) \
                 : "r"((a)[0]),"r"((a)[1]),"r"((a)[2]),"r"((a)[3]), \
                   "r"((b)[0]),"r"((b)[1]))

// ---------------------------------------------------------------------------
// fp32 -> bf16 hi/lo split
// ---------------------------------------------------------------------------
__global__ void split_kernel(const float* __restrict__ s,
                             __nv_bfloat16* __restrict__ hi,
                             __nv_bfloat16* __restrict__ lo, int n4)
{
    int i = blockIdx.x * blockDim.x + threadIdx.x;
    if (i >= n4) return;
    float4 x = ((const float4*)s)[i];
    float v[4] = {x.x, x.y, x.z, x.w};
    uint32_t uh[2] = {0, 0}, ul[2] = {0, 0};
#pragma unroll
    for (int j = 0; j < 4; j++) {
        __nv_bfloat16 h = __float2bfloat16(v[j]);
        __nv_bfloat16 l = __float2bfloat16(v[j] - __bfloat162float(h));
        uh[j >> 1] |= (uint32_t)__bfloat16_as_ushort(h) << ((j & 1) * 16);
        ul[j >> 1] |= (uint32_t)__bfloat16_as_ushort(l) << ((j & 1) * 16);
    }
    ((uint2*)hi)[i] = make_uint2(uh[0], uh[1]);
    ((uint2*)lo)[i] = make_uint2(ul[0], ul[1]);
}

// ---------------------------------------------------------------------------
// bf16x3 mma.sync GEMM (NT): C[m][n] = sum_k A[m][k]*W[n][k], fp32 accum
// CTA 128x128, 8 warps (2m x 4n), warp tile 64x32, K-chunk 32, 3-stage cp.async
// smem rows padded to 80B (conflict-free ldmatrix)
// ---------------------------------------------------------------------------
#define GKC   32
#define GNIT  (HID / GKC)     // 64
#define ROWB  80
#define TILEB (128 * ROWB)    // 10240
#define STAGEB (4 * TILEB)    // 40960: Ahi, Alo, Whi, Wlo
#define GSMEM (3 * STAGEB)    // 122880

__device__ __forceinline__ void g_load_stage(
    uint32_t sb, const char* A0, const char* A1,
    const char* W0, const char* W1, int tid)
{
    // A0/A1/W0/W1 already point at (tile_row0, k0) in global, row stride 4096B
#pragma unroll
    for (int p = 0; p < 2; p++) {
        int q = tid + 256 * p;           // 0..511
        int row = q >> 2;
        int c = q & 3;
        uint32_t so = sb + row * ROWB + c * 16;
        size_t go = (size_t)row * (HID * 2) + c * 16;
        CP16(so,             A0 + go);
        CP16(so + TILEB,     A1 + go);
        CP16(so + 2 * TILEB, W0 + go);
        CP16(so + 3 * TILEB, W1 + go);
    }
}

__global__ __launch_bounds__(256) void gemm_mma(
    const __nv_bfloat16* __restrict__ Ahi, const __nv_bfloat16* __restrict__ Alo,
    const __nv_bfloat16* __restrict__ Whi, const __nv_bfloat16* __restrict__ Wlo,
    float* __restrict__ C)
{
    extern __shared__ char sm[];
    const uint32_t smb = smem_u32(sm);
    const int tid = threadIdx.x;
    const int wid = tid >> 5, l = tid & 31;
    const int bm = blockIdx.y * 128;
    const int bn = blockIdx.x * 128;
    const int wm = (wid >> 2) * 64;      // warp m offset in tile
    const int wn = (wid & 3) * 32;       // warp n offset in tile

    const char* A0 = (const char*)(Ahi + (size_t)bm * HID);
    const char* A1 = (const char*)(Alo + (size_t)bm * HID);
    const char* W0 = (const char*)(Whi + (size_t)bn * HID);
    const char* W1 = (const char*)(Wlo + (size_t)bn * HID);

    float acc[4][4][4];
#pragma unroll
    for (int mt = 0; mt < 4; mt++)
#pragma unroll
        for (int nt = 0; nt < 4; nt++)
#pragma unroll
            for (int r = 0; r < 4; r++) acc[mt][nt][r] = 0.f;

    // per-lane ldmatrix base offsets
    const uint32_t aoff = (uint32_t)((wm + (l & 15)) * ROWB + (l >> 4) * 16);
    const uint32_t boff = (uint32_t)(2 * TILEB + (wn + (l & 7)) * ROWB +
                                     ((l >> 3) & 1) * 16);

    // prologue: stages 0,1
    g_load_stage(smb,              A0,              A1,              W0,              W1,              tid);
    CP_COMMIT();
    g_load_stage(smb + STAGEB, A0 + GKC * 2, A1 + GKC * 2, W0 + GKC * 2, W1 + GKC * 2, tid);
    CP_COMMIT();

    for (int it = 0; it < GNIT; it++) {
        CP_WAIT1();
        __syncthreads();
        if (it + 2 < GNIT) {
            size_t ko = (size_t)(it + 2) * GKC * 2;
            g_load_stage(smb + ((it + 2) % 3) * STAGEB,
                         A0 + ko, A1 + ko, W0 + ko, W1 + ko, tid);
        }
        CP_COMMIT();

        const uint32_t st = smb + (it % 3) * STAGEB;
#pragma unroll
        for (int s = 0; s < 2; s++) {
            uint32_t bh[4][2], bl[4][2];
#pragma unroll
            for (int nt = 0; nt < 4; nt++) {
                uint32_t ba = st + boff + nt * 8 * ROWB + s * 32;
                LDSM2(bh[nt][0], bh[nt][1], ba);
                LDSM2(bl[nt][0], bl[nt][1], ba + TILEB);
            }
#pragma unroll
            for (int mt = 0; mt < 4; mt++) {
                uint32_t ah[4], al[4];
                uint32_t aa = st + aoff + mt * 16 * ROWB + s * 32;
                LDSM4(ah[0], ah[1], ah[2], ah[3], aa);
                LDSM4(al[0], al[1], al[2], al[3], aa + TILEB);
#pragma unroll
                for (int nt = 0; nt < 4; nt++) {
                    MMA16816(acc[mt][nt], ah, bh[nt]);
                    MMA16816(acc[mt][nt], ah, bl[nt]);
                    MMA16816(acc[mt][nt], al, bh[nt]);
                }
            }
        }
    }

    // epilogue: direct fp32 stores
    const int r0 = bm + wm + (l >> 2);
    const int c0 = bn + wn + (l & 3) * 2;
#pragma unroll
    for (int mt = 0; mt < 4; mt++)
#pragma unroll
        for (int nt = 0; nt < 4; nt++) {
            float* p0 = C + (size_t)(r0 + mt * 16) * HID + c0 + nt * 8;
            *(float2*)p0 = make_float2(acc[mt][nt][0], acc[mt][nt][1]);
            float* p1 = p0 + 8 * HID;
            *(float2*)p1 = make_float2(acc[mt][nt][2], acc[mt][nt][3]);
        }
}

// ---------------------------------------------------------------------------
// RoPE in-place on g_q, g_k
// ---------------------------------------------------------------------------
__global__ void rope_kernel()
{
    unsigned idx = blockIdx.x * blockDim.x + threadIdx.x;
    int d = idx & 63;
    int h = (idx >> 6) & 15;
    int s = (idx >> 10) & 2047;
    int b = idx >> 21;
    if (b >= BB) return;
    size_t base = ((size_t)(b * SEQ + s)) * HID + h * HD;

    float inv = expf(-logf(10000.f) * (float)d * (1.f / 64.f));
    float ang = (float)s * inv;
    float c = cosf(ang), sn = sinf(ang);

    float q1 = g_q[base + d], q2 = g_q[base + d + 64];
    g_q[base + d]      = q1 * c - q2 * sn;
    g_q[base + d + 64] = q2 * c + q1 * sn;

    float k1 = g_k[base + d], k2 = g_k[base + d + 64];
    g_k[base + d]      = k1 * c - k2 * sn;
    g_k[base + d + 64] = k2 * c + k1 * sn;
}

// ---------------------------------------------------------------------------
// Flash attention (fp32 FFMA, 64-row q tiles) — unchanged
// ---------------------------------------------------------------------------
#define ATT_SMEM_FLOATS (64*128 + 128*64 + 64*128 + 64*64)
#define ATT_SMEM_BYTES  (ATT_SMEM_FLOATS * 4)

__global__ __launch_bounds__(256, 2) void attn_kernel()
{
    extern __shared__ float sh[];
    float* Qs = sh;
    float* Kt = Qs + 64 * 128;
    float* Vs = Kt + 128 * 64;
    float* Ps = Vs + 64 * 128;

    const int qt = blockIdx.x;
    const int bh = blockIdx.y;
    const int b = bh >> 4, h = bh & 15;
    const int tid = threadIdx.x;
    const int tr = tid >> 4;
    const int tc = tid & 15;

    const float scale = 0.08838834764831844f;

    const float* Qg = g_q + ((size_t)b * SEQ + qt * 64) * HID + h * HD;
    const float* Kg = g_k + ((size_t)b * SEQ) * HID + h * HD;
    const float* Vg = g_v + ((size_t)b * SEQ) * HID + h * HD;

#pragma unroll
    for (int t = 0; t < 8; t++) {
        int f = tid + 256 * t;
        int row = f >> 5;
        int c4 = (f & 31) << 2;
        float4 q = *(const float4*)(Qg + (size_t)row * HID + c4);
        q.x *= scale; q.y *= scale; q.z *= scale; q.w *= scale;
        *(float4*)&Qs[row * 128 + c4] = q;
    }

    float m_[4], l_[4], o_[4][8];
#pragma unroll
    for (int i = 0; i < 4; i++) {
        m_[i] = -INFINITY; l_[i] = 0.f;
#pragma unroll
        for (int dd = 0; dd < 8; dd++) o_[i][dd] = 0.f;
    }

    for (int kt = 0; kt < SEQ / 64; kt++) {
        const float* Kp = Kg + (size_t)kt * 64 * HID;
        const float* Vp = Vg + (size_t)kt * 64 * HID;
#pragma unroll
        for (int t = 0; t < 8; t++) {
            int f = tid + 256 * t;
            int row = f >> 5;
            int c4 = (f & 31) << 2;
            float4 kv = *(const float4*)(Kp + (size_t)row * HID + c4);
            Kt[(c4 + 0) * 64 + row] = kv.x;
            Kt[(c4 + 1) * 64 + row] = kv.y;
            Kt[(c4 + 2) * 64 + row] = kv.z;
            Kt[(c4 + 3) * 64 + row] = kv.w;
            float4 vv = *(const float4*)(Vp + (size_t)row * HID + c4);
            *(float4*)&Vs[row * 128 + c4] = vv;
        }
        __syncthreads();

        float sacc[4][4];
#pragma unroll
        for (int i = 0; i < 4; i++)
#pragma unroll
            for (int j = 0; j < 4; j++) sacc[i][j] = 0.f;

#pragma unroll 4
        for (int d0 = 0; d0 < 128; d0 += 4) {
            float q[4][4], k[4][4];
#pragma unroll
            for (int i = 0; i < 4; i++)
                *(float4*)q[i] = *(const float4*)&Qs[(tr * 4 + i) * 128 + d0];
#pragma unroll
            for (int dd = 0; dd < 4; dd++)
                *(float4*)k[dd] = *(const float4*)&Kt[(d0 + dd) * 64 + tc * 4];
#pragma unroll
            for (int dd = 0; dd < 4; dd++)
#pragma unroll
                for (int i = 0; i < 4; i++)
#pragma unroll
                    for (int j = 0; j < 4; j++)
                        sacc[i][j] = fmaf(q[i][dd], k[dd][j], sacc[i][j]);
        }

#pragma unroll
        for (int i = 0; i < 4; i++) {
            float tm = fmaxf(fmaxf(sacc[i][0], sacc[i][1]),
                             fmaxf(sacc[i][2], sacc[i][3]));
            tm = fmaxf(tm, __shfl_xor_sync(0xffffffffu, tm, 1));
            tm = fmaxf(tm, __shfl_xor_sync(0xffffffffu, tm, 2));
            tm = fmaxf(tm, __shfl_xor_sync(0xffffffffu, tm, 4));
            tm = fmaxf(tm, __shfl_xor_sync(0xffffffffu, tm, 8));
            float mn = fmaxf(m_[i], tm);
            float corr = expf(m_[i] - mn);
            float rs = 0.f;
#pragma unroll
            for (int j = 0; j < 4; j++) {
                float p = expf(sacc[i][j] - mn);
                sacc[i][j] = p;
                rs += p;
            }
            rs += __shfl_xor_sync(0xffffffffu, rs, 1);
            rs += __shfl_xor_sync(0xffffffffu, rs, 2);
            rs += __shfl_xor_sync(0xffffffffu, rs, 4);
            rs += __shfl_xor_sync(0xffffffffu, rs, 8);
            l_[i] = l_[i] * corr + rs;
            m_[i] = mn;
#pragma unroll
            for (int dd = 0; dd < 8; dd++) o_[i][dd] *= corr;
            *(float4*)&Ps[(tr * 4 + i) * 64 + tc * 4] =
                make_float4(sacc[i][0], sacc[i][1], sacc[i][2], sacc[i][3]);
        }
        __syncthreads();

#pragma unroll 4
        for (int j0 = 0; j0 < 64; j0 += 4) {
            float p[4][4], v[4][8];
#pragma unroll
            for (int i = 0; i < 4; i++)
                *(float4*)p[i] = *(const float4*)&Ps[(tr * 4 + i) * 64 + j0];
#pragma unroll
            for (int jj = 0; jj < 4; jj++) {
                *(float4*)&v[jj][0] = *(const float4*)&Vs[(j0 + jj) * 128 + tc * 8];
                *(float4*)&v[jj][4] = *(const float4*)&Vs[(j0 + jj) * 128 + tc * 8 + 4];
            }
#pragma unroll
            for (int jj = 0; jj < 4; jj++)
#pragma unroll
                for (int i = 0; i < 4; i++)
#pragma unroll
                    for (int dd = 0; dd < 8; dd++)
                        o_[i][dd] = fmaf(p[i][jj], v[jj][dd], o_[i][dd]);
        }
        __syncthreads();
    }

    float* Og = g_att + ((size_t)b * SEQ + qt * 64) * HID + h * HD;
#pragma unroll
    for (int i = 0; i < 4; i++) {
        float inv = 1.f / l_[i];
        float* op = Og + (size_t)(tr * 4 + i) * HID + tc * 8;
        *(float4*)op = make_float4(o_[i][0] * inv, o_[i][1] * inv,
                                   o_[i][2] * inv, o_[i][3] * inv);
        *(float4*)(op + 4) = make_float4(o_[i][4] * inv, o_[i][5] * inv,
                                         o_[i][6] * inv, o_[i][7] * inv);
    }
}

// ---------------------------------------------------------------------------
extern "C" void kernel_launch(void* const* d_in, const int* in_sizes, int n_in,
                              void* d_out, int out_size)
{
    const float* x  = (const float*)d_in[0];
    const float* Wq = (const float*)d_in[1];
    const float* Wk = (const float*)d_in[2];
    const float* Wv = (const float*)d_in[3];
    const float* Wo = (const float*)d_in[4];
    float* out = (float*)d_out;

    float *q, *k, *v, *att;
    cudaGetSymbolAddress((void**)&q,   g_q);
    cudaGetSymbolAddress((void**)&k,   g_k);
    cudaGetSymbolAddress((void**)&v,   g_v);
    cudaGetSymbolAddress((void**)&att, g_att);
    __nv_bfloat16 *xhi, *xlo, *ahi, *alo, *whi, *wlo;
    cudaGetSymbolAddress((void**)&xhi, g_xhi);
    cudaGetSymbolAddress((void**)&xlo, g_xlo);
    cudaGetSymbolAddress((void**)&ahi, g_ahi);
    cudaGetSymbolAddress((void**)&alo, g_alo);
    cudaGetSymbolAddress((void**)&whi, g_whi);
    cudaGetSymbolAddress((void**)&wlo, g_wlo);

    const size_t wsz = (size_t)HID * HID;
    const int n4x = (MROWS * HID) / 4;
    const int n4w = (HID * HID) / 4;

    cudaFuncSetAttribute(gemm_mma,
                         cudaFuncAttributeMaxDynamicSharedMemorySize, GSMEM);
    cudaFuncSetAttribute(attn_kernel,
                         cudaFuncAttributeMaxDynamicSharedMemorySize,
                         ATT_SMEM_BYTES);

    split_kernel<<<n4x / 256, 256>>>(x,  xhi, xlo, n4x);
    split_kernel<<<n4w / 256, 256>>>(Wq, whi + 0 * wsz, wlo + 0 * wsz, n4w);
    split_kernel<<<n4w / 256, 256>>>(Wk, whi + 1 * wsz, wlo + 1 * wsz, n4w);
    split_kernel<<<n4w / 256, 256>>>(Wv, whi + 2 * wsz, wlo + 2 * wsz, n4w);
    split_kernel<<<n4w / 256, 256>>>(Wo, whi + 3 * wsz, wlo + 3 * wsz, n4w);

    dim3 gg(HID / 128, MROWS / 128);  // (16, 32)
    gemm_mma<<<gg, 256, GSMEM>>>(xhi, xlo, whi + 0 * wsz, wlo + 0 * wsz, q);
    gemm_mma<<<gg, 256, GSMEM>>>(xhi, xlo, whi + 1 * wsz, wlo + 1 * wsz, k);
    gemm_mma<<<gg, 256, GSMEM>>>(xhi, xlo, whi + 2 * wsz, wlo + 2 * wsz, v);

    rope_kernel<<<(1 << 22) / 256, 256>>>();

    attn_kernel<<<dim3(SEQ / 64, BB * NH), 256, ATT_SMEM_BYTES>>>();

    split_kernel<<<n4x / 256, 256>>>(att, ahi, alo, n4x);
    gemm_mma<<<gg, 256, GSMEM>>>(ahi, alo, whi + 3 * wsz, wlo + 3 * wsz, out);
}

// round 6
// speedup vs baseline: 2.9545x; 2.0138x over previous
#include <cuda_runtime.h>
#include <cuda_bf16.h>
#include <math.h>
#include <stdint.h>

#define BB 2
#define SEQ 2048
#define HID 2048
#define NH 16
#define HD 128
#define MROWS (BB*SEQ)   // 4096

// ---------------------------------------------------------------------------
// scratch (allocation-free rule: __device__ globals)
// ---------------------------------------------------------------------------
__device__ float g_q[(size_t)MROWS * HID];
__device__ float g_k[(size_t)MROWS * HID];
__device__ float g_v[(size_t)MROWS * HID];

__device__ __nv_bfloat16 g_xhi[(size_t)MROWS * HID];
__device__ __nv_bfloat16 g_xlo[(size_t)MROWS * HID];
__device__ __nv_bfloat16 g_ahi[(size_t)MROWS * HID];
__device__ __nv_bfloat16 g_alo[(size_t)MROWS * HID];
__device__ __nv_bfloat16 g_whi[4][(size_t)HID * HID];
__device__ __nv_bfloat16 g_wlo[4][(size_t)HID * HID];

// per-head bf16 splits: [bh][s][d]
__device__ __nv_bfloat16 g_qh[(size_t)BB*NH*SEQ*HD];
__device__ __nv_bfloat16 g_ql[(size_t)BB*NH*SEQ*HD];
__device__ __nv_bfloat16 g_kh[(size_t)BB*NH*SEQ*HD];
__device__ __nv_bfloat16 g_kl[(size_t)BB*NH*SEQ*HD];
__device__ __nv_bfloat16 g_vh[(size_t)BB*NH*SEQ*HD];
__device__ __nv_bfloat16 g_vl[(size_t)BB*NH*SEQ*HD];

__device__ __forceinline__ uint32_t smem_u32(const void* p) {
    uint32_t a;
    asm("{ .reg .u64 t; cvta.to.shared.u64 t, %1; cvt.u32.u64 %0, t; }"
        : "=r"(a) : "l"(p));
    return a;
}

#define CP16(sm, gp) \
    asm volatile("cp.async.cg.shared.global [%0], [%1], 16;" \
                 :: "r"(sm), "l"(gp) : "memory")
#define CP_COMMIT() asm volatile("cp.async.commit_group;" ::: "memory")
#define CP_WAIT1()  asm volatile("cp.async.wait_group 1;" ::: "memory")
#define CP_WAIT0()  asm volatile("cp.async.wait_group 0;" ::: "memory")

#define LDSM4(r0,r1,r2,r3, addr) \
    asm volatile("ldmatrix.sync.aligned.m8n8.x4.shared.b16 {%0,%1,%2,%3}, [%4];" \
                 : "=r"(r0),"=r"(r1),"=r"(r2),"=r"(r3) : "r"(addr))
#define LDSM4T(r0,r1,r2,r3, addr) \
    asm volatile("ldmatrix.sync.aligned.m8n8.x4.trans.shared.b16 {%0,%1,%2,%3}, [%4];" \
                 : "=r"(r0),"=r"(r1),"=r"(r2),"=r"(r3) : "r"(addr))
#define LDSM2(r0,r1, addr) \
    asm volatile("ldmatrix.sync.aligned.m8n8.x2.shared.b16 {%0,%1}, [%2];" \
                 : "=r"(r0),"=r"(r1) : "r"(addr))

#define MMA16816(c, a, b) \
    asm volatile("mma.sync.aligned.m16n8k16.row.col.f32.bf16.bf16.f32 " \
                 "{%0,%1,%2,%3},{%4,%5,%6,%7},{%8,%9},{%0,%1,%2,%3};" \
                 : "+f"((c)[0]),"+f"((c)[1]),"+f"((c)[2]),"+f"((c)[3]) \
                 : "r"((a)[0]),"r"((a)[1]),"r"((a)[2]),"r"((a)[3]), \
                   "r"((b)[0]),"r"((b)[1]))

#define MMA_B2(c, a, b0v, b1v) \
    asm volatile("mma.sync.aligned.m16n8k16.row.col.f32.bf16.bf16.f32 " \
                 "{%0,%1,%2,%3},{%4,%5,%6,%7},{%8,%9},{%0,%1,%2,%3};" \
                 : "+f"((c)[0]),"+f"((c)[1]),"+f"((c)[2]),"+f"((c)[3]) \
                 : "r"((a)[0]),"r"((a)[1]),"r"((a)[2]),"r"((a)[3]), \
                   "r"(b0v),"r"(b1v))

// split two fp32 into packed bf16x2 hi and lo
__device__ __forceinline__ void split2(float x0, float x1,
                                       uint32_t& hi, uint32_t& lo) {
    __nv_bfloat16 h0 = __float2bfloat16(x0), h1 = __float2bfloat16(x1);
    __nv_bfloat16 l0 = __float2bfloat16(x0 - __bfloat162float(h0));
    __nv_bfloat16 l1 = __float2bfloat16(x1 - __bfloat162float(h1));
    hi = (uint32_t)__bfloat16_as_ushort(h0) |
         ((uint32_t)__bfloat16_as_ushort(h1) << 16);
    lo = (uint32_t)__bfloat16_as_ushort(l0) |
         ((uint32_t)__bfloat16_as_ushort(l1) << 16);
}

// ---------------------------------------------------------------------------
// fp32 -> bf16 hi/lo split (for x and weights)
// ---------------------------------------------------------------------------
__global__ void split_kernel(const float* __restrict__ s,
                             __nv_bfloat16* __restrict__ hi,
                             __nv_bfloat16* __restrict__ lo, int n4)
{
    int i = blockIdx.x * blockDim.x + threadIdx.x;
    if (i >= n4) return;
    float4 x = ((const float4*)s)[i];
    uint32_t h0, l0, h1, l1;
    split2(x.x, x.y, h0, l0);
    split2(x.z, x.w, h1, l1);
    ((uint2*)hi)[i] = make_uint2(h0, h1);
    ((uint2*)lo)[i] = make_uint2(l0, l1);
}

// ---------------------------------------------------------------------------
// bf16x3 mma.sync GEMM (NT), unchanged from R3
// ---------------------------------------------------------------------------
#define GKC   32
#define GNIT  (HID / GKC)     // 64
#define ROWB  80
#define TILEB (128 * ROWB)    // 10240
#define STAGEB (4 * TILEB)    // 40960
#define GSMEM (3 * STAGEB)    // 122880

__device__ __forceinline__ void g_load_stage(
    uint32_t sb, const char* A0, const char* A1,
    const char* W0, const char* W1, int tid)
{
#pragma unroll
    for (int p = 0; p < 2; p++) {
        int q = tid + 256 * p;
        int row = q >> 2;
        int c = q & 3;
        uint32_t so = sb + row * ROWB + c * 16;
        size_t go = (size_t)row * (HID * 2) + c * 16;
        CP16(so,             A0 + go);
        CP16(so + TILEB,     A1 + go);
        CP16(so + 2 * TILEB, W0 + go);
        CP16(so + 3 * TILEB, W1 + go);
    }
}

__global__ __launch_bounds__(256) void gemm_mma(
    const __nv_bfloat16* __restrict__ Ahi, const __nv_bfloat16* __restrict__ Alo,
    const __nv_bfloat16* __restrict__ Whi, const __nv_bfloat16* __restrict__ Wlo,
    float* __restrict__ C)
{
    extern __shared__ char sm[];
    const uint32_t smb = smem_u32(sm);
    const int tid = threadIdx.x;
    const int wid = tid >> 5, l = tid & 31;
    const int bm = blockIdx.y * 128;
    const int bn = blockIdx.x * 128;
    const int wm = (wid >> 2) * 64;
    const int wn = (wid & 3) * 32;

    const char* A0 = (const char*)(Ahi + (size_t)bm * HID);
    const char* A1 = (const char*)(Alo + (size_t)bm * HID);
    const char* W0 = (const char*)(Whi + (size_t)bn * HID);
    const char* W1 = (const char*)(Wlo + (size_t)bn * HID);

    float acc[4][4][4];
#pragma unroll
    for (int mt = 0; mt < 4; mt++)
#pragma unroll
        for (int nt = 0; nt < 4; nt++)
#pragma unroll
            for (int r = 0; r < 4; r++) acc[mt][nt][r] = 0.f;

    const uint32_t aoff = (uint32_t)((wm + (l & 15)) * ROWB + (l >> 4) * 16);
    const uint32_t boff = (uint32_t)(2 * TILEB + (wn + (l & 7)) * ROWB +
                                     ((l >> 3) & 1) * 16);

    g_load_stage(smb,          A0,            A1,            W0,            W1,            tid);
    CP_COMMIT();
    g_load_stage(smb + STAGEB, A0 + GKC * 2,  A1 + GKC * 2,  W0 + GKC * 2,  W1 + GKC * 2,  tid);
    CP_COMMIT();

    for (int it = 0; it < GNIT; it++) {
        CP_WAIT1();
        __syncthreads();
        if (it + 2 < GNIT) {
            size_t ko = (size_t)(it + 2) * GKC * 2;
            g_load_stage(smb + ((it + 2) % 3) * STAGEB,
                         A0 + ko, A1 + ko, W0 + ko, W1 + ko, tid);
        }
        CP_COMMIT();

        const uint32_t st = smb + (it % 3) * STAGEB;
#pragma unroll
        for (int s = 0; s < 2; s++) {
            uint32_t bh[4][2], bl[4][2];
#pragma unroll
            for (int nt = 0; nt < 4; nt++) {
                uint32_t ba = st + boff + nt * 8 * ROWB + s * 32;
                LDSM2(bh[nt][0], bh[nt][1], ba);
                LDSM2(bl[nt][0], bl[nt][1], ba + TILEB);
            }
#pragma unroll
            for (int mt = 0; mt < 4; mt++) {
                uint32_t ah[4], al[4];
                uint32_t aa = st + aoff + mt * 16 * ROWB + s * 32;
                LDSM4(ah[0], ah[1], ah[2], ah[3], aa);
                LDSM4(al[0], al[1], al[2], al[3], aa + TILEB);
#pragma unroll
                for (int nt = 0; nt < 4; nt++) {
                    MMA16816(acc[mt][nt], ah, bh[nt]);
                    MMA16816(acc[mt][nt], ah, bl[nt]);
                    MMA16816(acc[mt][nt], al, bh[nt]);
                }
            }
        }
    }

    const int r0 = bm + wm + (l >> 2);
    const int c0 = bn + wn + (l & 3) * 2;
#pragma unroll
    for (int mt = 0; mt < 4; mt++)
#pragma unroll
        for (int nt = 0; nt < 4; nt++) {
            float* p0 = C + (size_t)(r0 + mt * 16) * HID + c0 + nt * 8;
            *(float2*)p0 = make_float2(acc[mt][nt][0], acc[mt][nt][1]);
            float* p1 = p0 + 8 * HID;
            *(float2*)p1 = make_float2(acc[mt][nt][2], acc[mt][nt][3]);
        }
}

// ---------------------------------------------------------------------------
// prep: RoPE(q,k) + q*=1/sqrt(HD) + fp32->bf16 hi/lo split + per-head layout
// thread: (b, s, h, t2) handles d = {2t2, 2t2+1} and pair {d+64, d+65}
// ---------------------------------------------------------------------------
__global__ void prep_kernel()
{
    unsigned idx = blockIdx.x * blockDim.x + threadIdx.x;   // 2^21 threads
    int t2 = idx & 31;
    int h  = (idx >> 5) & 15;
    int s  = (idx >> 9) & 2047;
    int b  = idx >> 20;
    if (b >= BB) return;
    const int d0 = t2 * 2;
    const float scale = 0.08838834764831844f;  // 1/sqrt(128)

    size_t src = ((size_t)(b * SEQ + s)) * HID + h * HD;
    size_t dst = ((size_t)((b * NH + h) * SEQ + s)) * HD;

    float a0 = (float)s * expf(-logf(10000.f) * (float)d0       * (1.f / 64.f));
    float a1 = (float)s * expf(-logf(10000.f) * (float)(d0 + 1) * (1.f / 64.f));
    float c0 = cosf(a0), s0 = sinf(a0);
    float c1 = cosf(a1), s1 = sinf(a1);

    // Q with rope + scale
    {
        float xl0 = g_q[src + d0],      xl1 = g_q[src + d0 + 1];
        float xu0 = g_q[src + d0 + 64], xu1 = g_q[src + d0 + 65];
        float r0 = (xl0 * c0 - xu0 * s0) * scale;
        float r1 = (xl1 * c1 - xu1 * s1) * scale;
        float u0 = (xu0 * c0 + xl0 * s0) * scale;
        float u1 = (xu1 * c1 + xl1 * s1) * scale;
        uint32_t hi, lo;
        split2(r0, r1, hi, lo);
        *(uint32_t*)&g_qh[dst + d0] = hi;  *(uint32_t*)&g_ql[dst + d0] = lo;
        split2(u0, u1, hi, lo);
        *(uint32_t*)&g_qh[dst + d0 + 64] = hi;  *(uint32_t*)&g_ql[dst + d0 + 64] = lo;
    }
    // K with rope
    {
        float xl0 = g_k[src + d0],      xl1 = g_k[src + d0 + 1];
        float xu0 = g_k[src + d0 + 64], xu1 = g_k[src + d0 + 65];
        float r0 = xl0 * c0 - xu0 * s0;
        float r1 = xl1 * c1 - xu1 * s1;
        float u0 = xu0 * c0 + xl0 * s0;
        float u1 = xu1 * c1 + xl1 * s1;
        uint32_t hi, lo;
        split2(r0, r1, hi, lo);
        *(uint32_t*)&g_kh[dst + d0] = hi;  *(uint32_t*)&g_kl[dst + d0] = lo;
        split2(u0, u1, hi, lo);
        *(uint32_t*)&g_kh[dst + d0 + 64] = hi;  *(uint32_t*)&g_kl[dst + d0 + 64] = lo;
    }
    // V plain split
    {
        uint32_t hi, lo;
        split2(g_v[src + d0], g_v[src + d0 + 1], hi, lo);
        *(uint32_t*)&g_vh[dst + d0] = hi;  *(uint32_t*)&g_vl[dst + d0] = lo;
        split2(g_v[src + d0 + 64], g_v[src + d0 + 65], hi, lo);
        *(uint32_t*)&g_vh[dst + d0 + 64] = hi;  *(uint32_t*)&g_vl[dst + d0 + 64] = lo;
    }
}

// ---------------------------------------------------------------------------
// Flash attention via mma.sync bf16x3
// CTA: 128 q-rows x one (b,h); 8 warps x m16; 64-key chunks; 2-stage cp.async
// smem rows padded to 272 B (conflict-free ldmatrix)
// ---------------------------------------------------------------------------
#define ACH 64
#define NCH (SEQ / ACH)       // 32
#define RB  272
#define QSM (128 * RB)        // 34816
#define KSM (64 * RB)         // 17408
#define QLOFF  34816
#define STOFF  69632
#define STSZ   69632          // K hi/lo + V hi/lo
#define ATT_SM (STOFF + 2 * STSZ)   // 208896

__device__ __forceinline__ void att_load_kv(
    uint32_t stbase, const char* KH, const char* KL,
    const char* VH, const char* VL, int ck, int tid)
{
#pragma unroll
    for (int p = 0; p < 4; p++) {
        int idx = tid + 256 * p;            // 0..1023
        int row = idx >> 4;                 // 0..63
        int c = idx & 15;
        uint32_t off = row * RB + c * 16;
        size_t g = (size_t)(ck * 64 + row) * 256 + c * 16;
        CP16(stbase + off,                 KH + g);
        CP16(stbase + 17408 + off,         KL + g);
        CP16(stbase + 34816 + off,         VH + g);
        CP16(stbase + 52224 + off,         VL + g);
    }
}

__global__ __launch_bounds__(256) void attn_mma()
{
    extern __shared__ char sm[];
    const uint32_t smb = smem_u32(sm);
    const int tid = threadIdx.x;
    const int w = tid >> 5, l = tid & 31;
    const int qt = blockIdx.x;              // 0..15
    const int bh = blockIdx.y;              // 0..31
    const int b = bh >> 4, h = bh & 15;

    const char* QHg = (const char*)(g_qh + ((size_t)bh * SEQ + qt * 128) * HD);
    const char* QLg = (const char*)(g_ql + ((size_t)bh * SEQ + qt * 128) * HD);
    const char* KHg = (const char*)(g_kh + (size_t)bh * SEQ * HD);
    const char* KLg = (const char*)(g_kl + (size_t)bh * SEQ * HD);
    const char* VHg = (const char*)(g_vh + (size_t)bh * SEQ * HD);
    const char* VLg = (const char*)(g_vl + (size_t)bh * SEQ * HD);

    // load Q hi/lo (128 rows x 256 B each)
#pragma unroll
    for (int p = 0; p < 8; p++) {
        int idx = tid + 256 * p;            // 0..2047
        int row = idx >> 4;
        int c = idx & 15;
        uint32_t off = row * RB + c * 16;
        size_t g = (size_t)row * 256 + c * 16;
        CP16(smb + off,         QHg + g);
        CP16(smb + QLOFF + off, QLg + g);
    }
    CP_COMMIT();
    att_load_kv(smb + STOFF, KHg, KLg, VHg, VLg, 0, tid);
    CP_COMMIT();

    float sacc[8][4], oacc[16][4];
    float m0 = -1e30f, m1 = -1e30f, l0 = 0.f, l1 = 0.f;
#pragma unroll
    for (int nt = 0; nt < 16; nt++)
#pragma unroll
        for (int r = 0; r < 4; r++) oacc[nt][r] = 0.f;

    // ldmatrix base offsets
    const uint32_t qa = smb + (w * 16 + (l & 15)) * RB + (l >> 4) * 16;
    const uint32_t krow = (l & 7) + ((l >> 4) & 1) * 8;   // K B-frag row term
    const uint32_t kcol = ((l >> 3) & 1) * 16;            // K B-frag d-half bytes
    const uint32_t vrow = (l & 7) + ((l >> 3) & 1) * 8;   // V B-frag key term
    const uint32_t vcol = ((l >> 4) & 1) * 16;            // V B-frag d-half bytes

    for (int it = 0; it < NCH; it++) {
        if (it + 1 < NCH) {
            att_load_kv(smb + STOFF + ((it + 1) & 1) * STSZ,
                        KHg, KLg, VHg, VLg, it + 1, tid);
            CP_COMMIT();
            CP_WAIT1();
        } else {
            CP_WAIT0();
        }
        __syncthreads();

        const uint32_t st = smb + STOFF + (it & 1) * STSZ;

        // ---- S = Q K^T (bf16x3) ----
#pragma unroll
        for (int nt = 0; nt < 8; nt++)
#pragma unroll
            for (int r = 0; r < 4; r++) sacc[nt][r] = 0.f;

#pragma unroll
        for (int kc = 0; kc < 8; kc++) {
            uint32_t ah[4], al[4];
            LDSM4(ah[0], ah[1], ah[2], ah[3], qa + kc * 32);
            LDSM4(al[0], al[1], al[2], al[3], qa + QLOFF + kc * 32);
#pragma unroll
            for (int g = 0; g < 4; g++) {
                uint32_t ka = st + (g * 16 + krow) * RB + kc * 32 + kcol;
                uint32_t bh_[4], bl_[4];
                LDSM4(bh_[0], bh_[1], bh_[2], bh_[3], ka);
                LDSM4(bl_[0], bl_[1], bl_[2], bl_[3], ka + 17408);
                MMA_B2(sacc[2 * g],     ah, bh_[0], bh_[1]);
                MMA_B2(sacc[2 * g + 1], ah, bh_[2], bh_[3]);
                MMA_B2(sacc[2 * g],     ah, bl_[0], bl_[1]);
                MMA_B2(sacc[2 * g + 1], ah, bl_[2], bl_[3]);
                MMA_B2(sacc[2 * g],     al, bh_[0], bh_[1]);
                MMA_B2(sacc[2 * g + 1], al, bh_[2], bh_[3]);
            }
        }

        // ---- online softmax ----
        float mx0 = -1e30f, mx1 = -1e30f;
#pragma unroll
        for (int nt = 0; nt < 8; nt++) {
            mx0 = fmaxf(mx0, fmaxf(sacc[nt][0], sacc[nt][1]));
            mx1 = fmaxf(mx1, fmaxf(sacc[nt][2], sacc[nt][3]));
        }
        mx0 = fmaxf(mx0, __shfl_xor_sync(0xffffffffu, mx0, 1));
        mx0 = fmaxf(mx0, __shfl_xor_sync(0xffffffffu, mx0, 2));
        mx1 = fmaxf(mx1, __shfl_xor_sync(0xffffffffu, mx1, 1));
        mx1 = fmaxf(mx1, __shfl_xor_sync(0xffffffffu, mx1, 2));
        float mn0 = fmaxf(m0, mx0), mn1 = fmaxf(m1, mx1);
        float corr0 = __expf(m0 - mn0), corr1 = __expf(m1 - mn1);
        m0 = mn0; m1 = mn1;
        float rs0 = 0.f, rs1 = 0.f;
#pragma unroll
        for (int nt = 0; nt < 8; nt++) {
            sacc[nt][0] = __expf(sacc[nt][0] - mn0);
            sacc[nt][1] = __expf(sacc[nt][1] - mn0);
            sacc[nt][2] = __expf(sacc[nt][2] - mn1);
            sacc[nt][3] = __expf(sacc[nt][3] - mn1);
            rs0 += sacc[nt][0] + sacc[nt][1];
            rs1 += sacc[nt][2] + sacc[nt][3];
        }
        rs0 += __shfl_xor_sync(0xffffffffu, rs0, 1);
        rs0 += __shfl_xor_sync(0xffffffffu, rs0, 2);
        rs1 += __shfl_xor_sync(0xffffffffu, rs1, 1);
        rs1 += __shfl_xor_sync(0xffffffffu, rs1, 2);
        l0 = l0 * corr0 + rs0;
        l1 = l1 * corr1 + rs1;
#pragma unroll
        for (int nt = 0; nt < 16; nt++) {
            oacc[nt][0] *= corr0; oacc[nt][1] *= corr0;
            oacc[nt][2] *= corr1; oacc[nt][3] *= corr1;
        }

        // ---- O += P V (bf16x3) ----
#pragma unroll
        for (int t = 0; t < 4; t++) {
            uint32_t pah[4], pal[4];
            split2(sacc[2 * t][0],     sacc[2 * t][1],     pah[0], pal[0]);
            split2(sacc[2 * t][2],     sacc[2 * t][3],     pah[1], pal[1]);
            split2(sacc[2 * t + 1][0], sacc[2 * t + 1][1], pah[2], pal[2]);
            split2(sacc[2 * t + 1][2], sacc[2 * t + 1][3], pah[3], pal[3]);
#pragma unroll
            for (int n = 0; n < 8; n++) {
                uint32_t va = st + 34816 + (t * 16 + vrow) * RB + n * 32 + vcol;
                uint32_t bh_[4], bl_[4];
                LDSM4T(bh_[0], bh_[1], bh_[2], bh_[3], va);
                LDSM4T(bl_[0], bl_[1], bl_[2], bl_[3], va + 17408);
                MMA_B2(oacc[2 * n],     pah, bh_[0], bh_[1]);
                MMA_B2(oacc[2 * n + 1], pah, bh_[2], bh_[3]);
                MMA_B2(oacc[2 * n],     pah, bl_[0], bl_[1]);
                MMA_B2(oacc[2 * n + 1], pah, bl_[2], bl_[3]);
                MMA_B2(oacc[2 * n],     pal, bh_[0], bh_[1]);
                MMA_B2(oacc[2 * n + 1], pal, bh_[2], bh_[3]);
            }
        }
        __syncthreads();
    }

    // ---- epilogue: normalize, split to bf16 hi/lo, store to g_ahi/g_alo ----
    const float inv0 = 1.f / l0, inv1 = 1.f / l1;
    const int row = qt * 128 + w * 16 + (l >> 2);
    size_t o0 = ((size_t)(b * SEQ) + row) * HID + h * HD + (l & 3) * 2;
#pragma unroll
    for (int nt = 0; nt < 16; nt++) {
        uint32_t hi, lo;
        split2(oacc[nt][0] * inv0, oacc[nt][1] * inv0, hi, lo);
        *(uint32_t*)&g_ahi[o0 + nt * 8] = hi;
        *(uint32_t*)&g_alo[o0 + nt * 8] = lo;
        split2(oacc[nt][2] * inv1, oacc[nt][3] * inv1, hi, lo);
        *(uint32_t*)&g_ahi[o0 + 8 * HID + nt * 8] = hi;
        *(uint32_t*)&g_alo[o0 + 8 * HID + nt * 8] = lo;
    }
}

// ---------------------------------------------------------------------------
extern "C" void kernel_launch(void* const* d_in, const int* in_sizes, int n_in,
                              void* d_out, int out_size)
{
    const float* x  = (const float*)d_in[0];
    const float* Wq = (const float*)d_in[1];
    const float* Wk = (const float*)d_in[2];
    const float* Wv = (const float*)d_in[3];
    const float* Wo = (const float*)d_in[4];
    float* out = (float*)d_out;

    float *q, *k, *v;
    cudaGetSymbolAddress((void**)&q, g_q);
    cudaGetSymbolAddress((void**)&k, g_k);
    cudaGetSymbolAddress((void**)&v, g_v);
    __nv_bfloat16 *xhi, *xlo, *ahi, *alo, *whi, *wlo;
    cudaGetSymbolAddress((void**)&xhi, g_xhi);
    cudaGetSymbolAddress((void**)&xlo, g_xlo);
    cudaGetSymbolAddress((void**)&ahi, g_ahi);
    cudaGetSymbolAddress((void**)&alo, g_alo);
    cudaGetSymbolAddress((void**)&whi, g_whi);
    cudaGetSymbolAddress((void**)&wlo, g_wlo);

    const size_t wsz = (size_t)HID * HID;
    const int n4x = (MROWS * HID) / 4;
    const int n4w = (HID * HID) / 4;

    cudaFuncSetAttribute(gemm_mma,
                         cudaFuncAttributeMaxDynamicSharedMemorySize, GSMEM);
    cudaFuncSetAttribute(attn_mma,
                         cudaFuncAttributeMaxDynamicSharedMemorySize, ATT_SM);

    split_kernel<<<n4x / 256, 256>>>(x,  xhi, xlo, n4x);
    split_kernel<<<n4w / 256, 256>>>(Wq, whi + 0 * wsz, wlo + 0 * wsz, n4w);
    split_kernel<<<n4w / 256, 256>>>(Wk, whi + 1 * wsz, wlo + 1 * wsz, n4w);
    split_kernel<<<n4w / 256, 256>>>(Wv, whi + 2 * wsz, wlo + 2 * wsz, n4w);
    split_kernel<<<n4w / 256, 256>>>(Wo, whi + 3 * wsz, wlo + 3 * wsz, n4w);

    dim3 gg(HID / 128, MROWS / 128);  // (16, 32)
    gemm_mma<<<gg, 256, GSMEM>>>(xhi, xlo, whi + 0 * wsz, wlo + 0 * wsz, q);
    gemm_mma<<<gg, 256, GSMEM>>>(xhi, xlo, whi + 1 * wsz, wlo + 1 * wsz, k);
    gemm_mma<<<gg, 256, GSMEM>>>(xhi, xlo, whi + 2 * wsz, wlo + 2 * wsz, v);

    prep_kernel<<<(1 << 21) / 256, 256>>>();

    attn_mma<<<dim3(SEQ / 128, BB * NH), 256, ATT_SM>>>();

    gemm_mma<<<gg, 256, GSMEM>>>(ahi, alo, whi + 3 * wsz, wlo + 3 * wsz, out);
}

// round 7
// speedup vs baseline: 3.3380x; 1.1298x over previous
#include <cuda_runtime.h>
#include <cuda_bf16.h>
#include <math.h>
#include <stdint.h>

#define BB 2
#define SEQ 2048
#define HID 2048
#define NH 16
#define HD 128
#define MROWS (BB*SEQ)   // 4096

// ---------------------------------------------------------------------------
// scratch (allocation-free rule: __device__ globals)
// ---------------------------------------------------------------------------
__device__ float g_q[(size_t)MROWS * HID];
__device__ float g_k[(size_t)MROWS * HID];
__device__ float g_v[(size_t)MROWS * HID];

__device__ __nv_bfloat16 g_xhi[(size_t)MROWS * HID];
__device__ __nv_bfloat16 g_xlo[(size_t)MROWS * HID];
__device__ __nv_bfloat16 g_ahi[(size_t)MROWS * HID];
__device__ __nv_bfloat16 g_alo[(size_t)MROWS * HID];
__device__ __nv_bfloat16 g_whi[4][(size_t)HID * HID];
__device__ __nv_bfloat16 g_wlo[4][(size_t)HID * HID];

// per-head bf16 splits: [bh][s][d]
__device__ __nv_bfloat16 g_qh[(size_t)BB*NH*SEQ*HD];
__device__ __nv_bfloat16 g_ql[(size_t)BB*NH*SEQ*HD];
__device__ __nv_bfloat16 g_kh[(size_t)BB*NH*SEQ*HD];
__device__ __nv_bfloat16 g_kl[(size_t)BB*NH*SEQ*HD];
__device__ __nv_bfloat16 g_vh[(size_t)BB*NH*SEQ*HD];
__device__ __nv_bfloat16 g_vl[(size_t)BB*NH*SEQ*HD];

__device__ __forceinline__ uint32_t smem_u32(const void* p) {
    uint32_t a;
    asm("{ .reg .u64 t; cvta.to.shared.u64 t, %1; cvt.u32.u64 %0, t; }"
        : "=r"(a) : "l"(p));
    return a;
}

#define CP16(sm, gp) \
    asm volatile("cp.async.cg.shared.global [%0], [%1], 16;" \
                 :: "r"(sm), "l"(gp) : "memory")
#define CP_COMMIT() asm volatile("cp.async.commit_group;" ::: "memory")
#define CP_WAIT1()  asm volatile("cp.async.wait_group 1;" ::: "memory")
#define CP_WAIT0()  asm volatile("cp.async.wait_group 0;" ::: "memory")

#define LDSM4(r0,r1,r2,r3, addr) \
    asm volatile("ldmatrix.sync.aligned.m8n8.x4.shared.b16 {%0,%1,%2,%3}, [%4];" \
                 : "=r"(r0),"=r"(r1),"=r"(r2),"=r"(r3) : "r"(addr))
#define LDSM4T(r0,r1,r2,r3, addr) \
    asm volatile("ldmatrix.sync.aligned.m8n8.x4.trans.shared.b16 {%0,%1,%2,%3}, [%4];" \
                 : "=r"(r0),"=r"(r1),"=r"(r2),"=r"(r3) : "r"(addr))
#define LDSM2(r0,r1, addr) \
    asm volatile("ldmatrix.sync.aligned.m8n8.x2.shared.b16 {%0,%1}, [%2];" \
                 : "=r"(r0),"=r"(r1) : "r"(addr))

#define MMA16816(c, a, b) \
    asm volatile("mma.sync.aligned.m16n8k16.row.col.f32.bf16.bf16.f32 " \
                 "{%0,%1,%2,%3},{%4,%5,%6,%7},{%8,%9},{%0,%1,%2,%3};" \
                 : "+f"((c)[0]),"+f"((c)[1]),"+f"((c)[2]),"+f"((c)[3]) \
                 : "r"((a)[0]),"r"((a)[1]),"r"((a)[2]),"r"((a)[3]), \
                   "r"((b)[0]),"r"((b)[1]))

#define MMA_B2(c, a, b0v, b1v) \
    asm volatile("mma.sync.aligned.m16n8k16.row.col.f32.bf16.bf16.f32 " \
                 "{%0,%1,%2,%3},{%4,%5,%6,%7},{%8,%9},{%0,%1,%2,%3};" \
                 : "+f"((c)[0]),"+f"((c)[1]),"+f"((c)[2]),"+f"((c)[3]) \
                 : "r"((a)[0]),"r"((a)[1]),"r"((a)[2]),"r"((a)[3]), \
                   "r"(b0v),"r"(b1v))

// split two fp32 into packed bf16x2 hi and lo
__device__ __forceinline__ void split2(float x0, float x1,
                                       uint32_t& hi, uint32_t& lo) {
    __nv_bfloat16 h0 = __float2bfloat16(x0), h1 = __float2bfloat16(x1);
    __nv_bfloat16 l0 = __float2bfloat16(x0 - __bfloat162float(h0));
    __nv_bfloat16 l1 = __float2bfloat16(x1 - __bfloat162float(h1));
    hi = (uint32_t)__bfloat16_as_ushort(h0) |
         ((uint32_t)__bfloat16_as_ushort(h1) << 16);
    lo = (uint32_t)__bfloat16_as_ushort(l0) |
         ((uint32_t)__bfloat16_as_ushort(l1) << 16);
}

// ---------------------------------------------------------------------------
// fp32 -> bf16 hi/lo split
// ---------------------------------------------------------------------------
__global__ void split_kernel(const float* __restrict__ s,
                             __nv_bfloat16* __restrict__ hi,
                             __nv_bfloat16* __restrict__ lo, int n4)
{
    int i = blockIdx.x * blockDim.x + threadIdx.x;
    if (i >= n4) return;
    float4 x = ((const float4*)s)[i];
    uint32_t h0, l0, h1, l1;
    split2(x.x, x.y, h0, l0);
    split2(x.z, x.w, h1, l1);
    ((uint2*)hi)[i] = make_uint2(h0, h1);
    ((uint2*)lo)[i] = make_uint2(l0, l1);
}

// ---------------------------------------------------------------------------
// bf16x3 mma.sync GEMM (NT): 2-stage cp.async, 2 CTAs/SM
// CTA 128x128, 8 warps (2m x 4n), warp tile 64x32, K-chunk 32
// blockIdx.z selects among up to 3 (W, C) pairs (QKV fusion)
// ---------------------------------------------------------------------------
#define GKC   32
#define GNIT  (HID / GKC)     // 64
#define ROWB  80
#define TILEB (128 * ROWB)    // 10240
#define STAGEB (4 * TILEB)    // 40960
#define GSMEM (2 * STAGEB)    // 81920

__device__ __forceinline__ void g_load_stage(
    uint32_t sb, const char* A0, const char* A1,
    const char* W0, const char* W1, int tid)
{
#pragma unroll
    for (int p = 0; p < 2; p++) {
        int q = tid + 256 * p;
        int row = q >> 2;
        int c = q & 3;
        uint32_t so = sb + row * ROWB + c * 16;
        size_t go = (size_t)row * (HID * 2) + c * 16;
        CP16(so,             A0 + go);
        CP16(so + TILEB,     A1 + go);
        CP16(so + 2 * TILEB, W0 + go);
        CP16(so + 3 * TILEB, W1 + go);
    }
}

__global__ __launch_bounds__(256, 2) void gemm_mma(
    const __nv_bfloat16* __restrict__ Ahi, const __nv_bfloat16* __restrict__ Alo,
    const __nv_bfloat16* __restrict__ Whi0, const __nv_bfloat16* __restrict__ Wlo0,
    float* __restrict__ C0,
    const __nv_bfloat16* __restrict__ Whi1, const __nv_bfloat16* __restrict__ Wlo1,
    float* __restrict__ C1,
    const __nv_bfloat16* __restrict__ Whi2, const __nv_bfloat16* __restrict__ Wlo2,
    float* __restrict__ C2)
{
    extern __shared__ char sm[];
    const uint32_t smb = smem_u32(sm);
    const int tid = threadIdx.x;
    const int wid = tid >> 5, l = tid & 31;
    const int bm = blockIdx.y * 128;
    const int bn = blockIdx.x * 128;
    const int z = blockIdx.z;
    const int wm = (wid >> 2) * 64;
    const int wn = (wid & 3) * 32;

    const __nv_bfloat16* Whi = (z == 0) ? Whi0 : (z == 1) ? Whi1 : Whi2;
    const __nv_bfloat16* Wlo = (z == 0) ? Wlo0 : (z == 1) ? Wlo1 : Wlo2;
    float* C = (z == 0) ? C0 : (z == 1) ? C1 : C2;

    const char* A0 = (const char*)(Ahi + (size_t)bm * HID);
    const char* A1 = (const char*)(Alo + (size_t)bm * HID);
    const char* W0 = (const char*)(Whi + (size_t)bn * HID);
    const char* W1 = (const char*)(Wlo + (size_t)bn * HID);

    float acc[4][4][4];
#pragma unroll
    for (int mt = 0; mt < 4; mt++)
#pragma unroll
        for (int nt = 0; nt < 4; nt++)
#pragma unroll
            for (int r = 0; r < 4; r++) acc[mt][nt][r] = 0.f;

    const uint32_t aoff = (uint32_t)((wm + (l & 15)) * ROWB + (l >> 4) * 16);
    const uint32_t boff = (uint32_t)(2 * TILEB + (wn + (l & 7)) * ROWB +
                                     ((l >> 3) & 1) * 16);

    g_load_stage(smb, A0, A1, W0, W1, tid);
    CP_COMMIT();

    for (int it = 0; it < GNIT; it++) {
        if (it + 1 < GNIT) {
            size_t ko = (size_t)(it + 1) * GKC * 2;
            g_load_stage(smb + ((it + 1) & 1) * STAGEB,
                         A0 + ko, A1 + ko, W0 + ko, W1 + ko, tid);
            CP_COMMIT();
            CP_WAIT1();
        } else {
            CP_WAIT0();
        }
        __syncthreads();

        const uint32_t st = smb + (it & 1) * STAGEB;
#pragma unroll
        for (int s = 0; s < 2; s++) {
            uint32_t bh[4][2], bl[4][2];
#pragma unroll
            for (int nt = 0; nt < 4; nt++) {
                uint32_t ba = st + boff + nt * 8 * ROWB + s * 32;
                LDSM2(bh[nt][0], bh[nt][1], ba);
                LDSM2(bl[nt][0], bl[nt][1], ba + TILEB);
            }
#pragma unroll
            for (int mt = 0; mt < 4; mt++) {
                uint32_t ah[4], al[4];
                uint32_t aa = st + aoff + mt * 16 * ROWB + s * 32;
                LDSM4(ah[0], ah[1], ah[2], ah[3], aa);
                LDSM4(al[0], al[1], al[2], al[3], aa + TILEB);
#pragma unroll
                for (int nt = 0; nt < 4; nt++) {
                    MMA16816(acc[mt][nt], ah, bh[nt]);
                    MMA16816(acc[mt][nt], ah, bl[nt]);
                    MMA16816(acc[mt][nt], al, bh[nt]);
                }
            }
        }
        __syncthreads();
    }

    const int r0 = bm + wm + (l >> 2);
    const int c0 = bn + wn + (l & 3) * 2;
#pragma unroll
    for (int mt = 0; mt < 4; mt++)
#pragma unroll
        for (int nt = 0; nt < 4; nt++) {
            float* p0 = C + (size_t)(r0 + mt * 16) * HID + c0 + nt * 8;
            *(float2*)p0 = make_float2(acc[mt][nt][0], acc[mt][nt][1]);
            float* p1 = p0 + 8 * HID;
            *(float2*)p1 = make_float2(acc[mt][nt][2], acc[mt][nt][3]);
        }
}

// ---------------------------------------------------------------------------
// prep: RoPE(q,k) + q*=1/sqrt(HD) + fp32->bf16 hi/lo split + per-head layout
// ---------------------------------------------------------------------------
__global__ void prep_kernel()
{
    unsigned idx = blockIdx.x * blockDim.x + threadIdx.x;
    int t2 = idx & 31;
    int h  = (idx >> 5) & 15;
    int s  = (idx >> 9) & 2047;
    int b  = idx >> 20;
    if (b >= BB) return;
    const int d0 = t2 * 2;
    const float scale = 0.08838834764831844f;

    size_t src = ((size_t)(b * SEQ + s)) * HID + h * HD;
    size_t dst = ((size_t)((b * NH + h) * SEQ + s)) * HD;

    float a0 = (float)s * expf(-logf(10000.f) * (float)d0       * (1.f / 64.f));
    float a1 = (float)s * expf(-logf(10000.f) * (float)(d0 + 1) * (1.f / 64.f));
    float c0 = cosf(a0), s0 = sinf(a0);
    float c1 = cosf(a1), s1 = sinf(a1);

    {
        float xl0 = g_q[src + d0],      xl1 = g_q[src + d0 + 1];
        float xu0 = g_q[src + d0 + 64], xu1 = g_q[src + d0 + 65];
        float r0 = (xl0 * c0 - xu0 * s0) * scale;
        float r1 = (xl1 * c1 - xu1 * s1) * scale;
        float u0 = (xu0 * c0 + xl0 * s0) * scale;
        float u1 = (xu1 * c1 + xl1 * s1) * scale;
        uint32_t hi, lo;
        split2(r0, r1, hi, lo);
        *(uint32_t*)&g_qh[dst + d0] = hi;  *(uint32_t*)&g_ql[dst + d0] = lo;
        split2(u0, u1, hi, lo);
        *(uint32_t*)&g_qh[dst + d0 + 64] = hi;  *(uint32_t*)&g_ql[dst + d0 + 64] = lo;
    }
    {
        float xl0 = g_k[src + d0],      xl1 = g_k[src + d0 + 1];
        float xu0 = g_k[src + d0 + 64], xu1 = g_k[src + d0 + 65];
        float r0 = xl0 * c0 - xu0 * s0;
        float r1 = xl1 * c1 - xu1 * s1;
        float u0 = xu0 * c0 + xl0 * s0;
        float u1 = xu1 * c1 + xl1 * s1;
        uint32_t hi, lo;
        split2(r0, r1, hi, lo);
        *(uint32_t*)&g_kh[dst + d0] = hi;  *(uint32_t*)&g_kl[dst + d0] = lo;
        split2(u0, u1, hi, lo);
        *(uint32_t*)&g_kh[dst + d0 + 64] = hi;  *(uint32_t*)&g_kl[dst + d0 + 64] = lo;
    }
    {
        uint32_t hi, lo;
        split2(g_v[src + d0], g_v[src + d0 + 1], hi, lo);
        *(uint32_t*)&g_vh[dst + d0] = hi;  *(uint32_t*)&g_vl[dst + d0] = lo;
        split2(g_v[src + d0 + 64], g_v[src + d0 + 65], hi, lo);
        *(uint32_t*)&g_vh[dst + d0 + 64] = hi;  *(uint32_t*)&g_vl[dst + d0 + 64] = lo;
    }
}

// ---------------------------------------------------------------------------
// Flash attention via mma.sync bf16x3 (unchanged from R6)
// ---------------------------------------------------------------------------
#define ACH 64
#define NCH (SEQ / ACH)       // 32
#define RB  272
#define QLOFF  34816
#define STOFF  69632
#define STSZ   69632
#define ATT_SM (STOFF + 2 * STSZ)   // 208896

__device__ __forceinline__ void att_load_kv(
    uint32_t stbase, const char* KH, const char* KL,
    const char* VH, const char* VL, int ck, int tid)
{
#pragma unroll
    for (int p = 0; p < 4; p++) {
        int idx = tid + 256 * p;
        int row = idx >> 4;
        int c = idx & 15;
        uint32_t off = row * RB + c * 16;
        size_t g = (size_t)(ck * 64 + row) * 256 + c * 16;
        CP16(stbase + off,         KH + g);
        CP16(stbase + 17408 + off, KL + g);
        CP16(stbase + 34816 + off, VH + g);
        CP16(stbase + 52224 + off, VL + g);
    }
}

__global__ __launch_bounds__(256) void attn_mma()
{
    extern __shared__ char sm[];
    const uint32_t smb = smem_u32(sm);
    const int tid = threadIdx.x;
    const int w = tid >> 5, l = tid & 31;
    const int qt = blockIdx.x;
    const int bh = blockIdx.y;
    const int b = bh >> 4, h = bh & 15;

    const char* QHg = (const char*)(g_qh + ((size_t)bh * SEQ + qt * 128) * HD);
    const char* QLg = (const char*)(g_ql + ((size_t)bh * SEQ + qt * 128) * HD);
    const char* KHg = (const char*)(g_kh + (size_t)bh * SEQ * HD);
    const char* KLg = (const char*)(g_kl + (size_t)bh * SEQ * HD);
    const char* VHg = (const char*)(g_vh + (size_t)bh * SEQ * HD);
    const char* VLg = (const char*)(g_vl + (size_t)bh * SEQ * HD);

#pragma unroll
    for (int p = 0; p < 8; p++) {
        int idx = tid + 256 * p;
        int row = idx >> 4;
        int c = idx & 15;
        uint32_t off = row * RB + c * 16;
        size_t g = (size_t)row * 256 + c * 16;
        CP16(smb + off,         QHg + g);
        CP16(smb + QLOFF + off, QLg + g);
    }
    CP_COMMIT();
    att_load_kv(smb + STOFF, KHg, KLg, VHg, VLg, 0, tid);
    CP_COMMIT();

    float sacc[8][4], oacc[16][4];
    float m0 = -1e30f, m1 = -1e30f, l0 = 0.f, l1 = 0.f;
#pragma unroll
    for (int nt = 0; nt < 16; nt++)
#pragma unroll
        for (int r = 0; r < 4; r++) oacc[nt][r] = 0.f;

    const uint32_t qa = smb + (w * 16 + (l & 15)) * RB + (l >> 4) * 16;
    const uint32_t krow = (l & 7) + ((l >> 4) & 1) * 8;
    const uint32_t kcol = ((l >> 3) & 1) * 16;
    const uint32_t vrow = (l & 7) + ((l >> 3) & 1) * 8;
    const uint32_t vcol = ((l >> 4) & 1) * 16;

    for (int it = 0; it < NCH; it++) {
        if (it + 1 < NCH) {
            att_load_kv(smb + STOFF + ((it + 1) & 1) * STSZ,
                        KHg, KLg, VHg, VLg, it + 1, tid);
            CP_COMMIT();
            CP_WAIT1();
        } else {
            CP_WAIT0();
        }
        __syncthreads();

        const uint32_t st = smb + STOFF + (it & 1) * STSZ;

#pragma unroll
        for (int nt = 0; nt < 8; nt++)
#pragma unroll
            for (int r = 0; r < 4; r++) sacc[nt][r] = 0.f;

#pragma unroll
        for (int kc = 0; kc < 8; kc++) {
            uint32_t ah[4], al[4];
            LDSM4(ah[0], ah[1], ah[2], ah[3], qa + kc * 32);
            LDSM4(al[0], al[1], al[2], al[3], qa + QLOFF + kc * 32);
#pragma unroll
            for (int g = 0; g < 4; g++) {
                uint32_t ka = st + (g * 16 + krow) * RB + kc * 32 + kcol;
                uint32_t bh_[4], bl_[4];
                LDSM4(bh_[0], bh_[1], bh_[2], bh_[3], ka);
                LDSM4(bl_[0], bl_[1], bl_[2], bl_[3], ka + 17408);
                MMA_B2(sacc[2 * g],     ah, bh_[0], bh_[1]);
                MMA_B2(sacc[2 * g + 1], ah, bh_[2], bh_[3]);
                MMA_B2(sacc[2 * g],     ah, bl_[0], bl_[1]);
                MMA_B2(sacc[2 * g + 1], ah, bl_[2], bl_[3]);
                MMA_B2(sacc[2 * g],     al, bh_[0], bh_[1]);
                MMA_B2(sacc[2 * g + 1], al, bh_[2], bh_[3]);
            }
        }

        float mx0 = -1e30f, mx1 = -1e30f;
#pragma unroll
        for (int nt = 0; nt < 8; nt++) {
            mx0 = fmaxf(mx0, fmaxf(sacc[nt][0], sacc[nt][1]));
            mx1 = fmaxf(mx1, fmaxf(sacc[nt][2], sacc[nt][3]));
        }
        mx0 = fmaxf(mx0, __shfl_xor_sync(0xffffffffu, mx0, 1));
        mx0 = fmaxf(mx0, __shfl_xor_sync(0xffffffffu, mx0, 2));
        mx1 = fmaxf(mx1, __shfl_xor_sync(0xffffffffu, mx1, 1));
        mx1 = fmaxf(mx1, __shfl_xor_sync(0xffffffffu, mx1, 2));
        float mn0 = fmaxf(m0, mx0), mn1 = fmaxf(m1, mx1);
        float corr0 = __expf(m0 - mn0), corr1 = __expf(m1 - mn1);
        m0 = mn0; m1 = mn1;
        float rs0 = 0.f, rs1 = 0.f;
#pragma unroll
        for (int nt = 0; nt < 8; nt++) {
            sacc[nt][0] = __expf(sacc[nt][0] - mn0);
            sacc[nt][1] = __expf(sacc[nt][1] - mn0);
            sacc[nt][2] = __expf(sacc[nt][2] - mn1);
            sacc[nt][3] = __expf(sacc[nt][3] - mn1);
            rs0 += sacc[nt][0] + sacc[nt][1];
            rs1 += sacc[nt][2] + sacc[nt][3];
        }
        rs0 += __shfl_xor_sync(0xffffffffu, rs0, 1);
        rs0 += __shfl_xor_sync(0xffffffffu, rs0, 2);
        rs1 += __shfl_xor_sync(0xffffffffu, rs1, 1);
        rs1 += __shfl_xor_sync(0xffffffffu, rs1, 2);
        l0 = l0 * corr0 + rs0;
        l1 = l1 * corr1 + rs1;
#pragma unroll
        for (int nt = 0; nt < 16; nt++) {
            oacc[nt][0] *= corr0; oacc[nt][1] *= corr0;
            oacc[nt][2] *= corr1; oacc[nt][3] *= corr1;
        }

#pragma unroll
        for (int t = 0; t < 4; t++) {
            uint32_t pah[4], pal[4];
            split2(sacc[2 * t][0],     sacc[2 * t][1],     pah[0], pal[0]);
            split2(sacc[2 * t][2],     sacc[2 * t][3],     pah[1], pal[1]);
            split2(sacc[2 * t + 1][0], sacc[2 * t + 1][1], pah[2], pal[2]);
            split2(sacc[2 * t + 1][2], sacc[2 * t + 1][3], pah[3], pal[3]);
#pragma unroll
            for (int n = 0; n < 8; n++) {
                uint32_t va = st + 34816 + (t * 16 + vrow) * RB + n * 32 + vcol;
                uint32_t bh_[4], bl_[4];
                LDSM4T(bh_[0], bh_[1], bh_[2], bh_[3], va);
                LDSM4T(bl_[0], bl_[1], bl_[2], bl_[3], va + 17408);
                MMA_B2(oacc[2 * n],     pah, bh_[0], bh_[1]);
                MMA_B2(oacc[2 * n + 1], pah, bh_[2], bh_[3]);
                MMA_B2(oacc[2 * n],     pah, bl_[0], bl_[1]);
                MMA_B2(oacc[2 * n + 1], pah, bl_[2], bl_[3]);
                MMA_B2(oacc[2 * n],     pal, bh_[0], bh_[1]);
                MMA_B2(oacc[2 * n + 1], pal, bh_[2], bh_[3]);
            }
        }
        __syncthreads();
    }

    const float inv0 = 1.f / l0, inv1 = 1.f / l1;
    const int row = qt * 128 + w * 16 + (l >> 2);
    size_t o0 = ((size_t)(b * SEQ) + row) * HID + h * HD + (l & 3) * 2;
#pragma unroll
    for (int nt = 0; nt < 16; nt++) {
        uint32_t hi, lo;
        split2(oacc[nt][0] * inv0, oacc[nt][1] * inv0, hi, lo);
        *(uint32_t*)&g_ahi[o0 + nt * 8] = hi;
        *(uint32_t*)&g_alo[o0 + nt * 8] = lo;
        split2(oacc[nt][2] * inv1, oacc[nt][3] * inv1, hi, lo);
        *(uint32_t*)&g_ahi[o0 + 8 * HID + nt * 8] = hi;
        *(uint32_t*)&g_alo[o0 + 8 * HID + nt * 8] = lo;
    }
}

// ---------------------------------------------------------------------------
extern "C" void kernel_launch(void* const* d_in, const int* in_sizes, int n_in,
                              void* d_out, int out_size)
{
    const float* x  = (const float*)d_in[0];
    const float* Wq = (const float*)d_in[1];
    const float* Wk = (const float*)d_in[2];
    const float* Wv = (const float*)d_in[3];
    const float* Wo = (const float*)d_in[4];
    float* out = (float*)d_out;

    float *q, *k, *v;
    cudaGetSymbolAddress((void**)&q, g_q);
    cudaGetSymbolAddress((void**)&k, g_k);
    cudaGetSymbolAddress((void**)&v, g_v);
    __nv_bfloat16 *xhi, *xlo, *ahi, *alo, *whi, *wlo;
    cudaGetSymbolAddress((void**)&xhi, g_xhi);
    cudaGetSymbolAddress((void**)&xlo, g_xlo);
    cudaGetSymbolAddress((void**)&ahi, g_ahi);
    cudaGetSymbolAddress((void**)&alo, g_alo);
    cudaGetSymbolAddress((void**)&whi, g_whi);
    cudaGetSymbolAddress((void**)&wlo, g_wlo);

    const size_t wsz = (size_t)HID * HID;
    const int n4x = (MROWS * HID) / 4;
    const int n4w = (HID * HID) / 4;

    cudaFuncSetAttribute(gemm_mma,
                         cudaFuncAttributeMaxDynamicSharedMemorySize, GSMEM);
    cudaFuncSetAttribute(attn_mma,
                         cudaFuncAttributeMaxDynamicSharedMemorySize, ATT_SM);

    split_kernel<<<n4x / 256, 256>>>(x,  xhi, xlo, n4x);
    split_kernel<<<n4w / 256, 256>>>(Wq, whi + 0 * wsz, wlo + 0 * wsz, n4w);
    split_kernel<<<n4w / 256, 256>>>(Wk, whi + 1 * wsz, wlo + 1 * wsz, n4w);
    split_kernel<<<n4w / 256, 256>>>(Wv, whi + 2 * wsz, wlo + 2 * wsz, n4w);
    split_kernel<<<n4w / 256, 256>>>(Wo, whi + 3 * wsz, wlo + 3 * wsz, n4w);

    // fused QKV projection: grid z = 3
    dim3 gqkv(HID / 128, MROWS / 128, 3);
    gemm_mma<<<gqkv, 256, GSMEM>>>(xhi, xlo,
                                   whi + 0 * wsz, wlo + 0 * wsz, q,
                                   whi + 1 * wsz, wlo + 1 * wsz, k,
                                   whi + 2 * wsz, wlo + 2 * wsz, v);

    prep_kernel<<<(1 << 21) / 256, 256>>>();

    attn_mma<<<dim3(SEQ / 128, BB * NH), 256, ATT_SM>>>();

    dim3 gg(HID / 128, MROWS / 128, 1);
    gemm_mma<<<gg, 256, GSMEM>>>(ahi, alo,
                                 whi + 3 * wsz, wlo + 3 * wsz, out,
                                 whi + 3 * wsz, wlo + 3 * wsz, out,
                                 whi + 3 * wsz, wlo + 3 * wsz, out);
}

// round 9
// speedup vs baseline: 3.5071x; 1.0507x over previous
#include <cuda_runtime.h>
#include <cuda_bf16.h>
#include <math.h>
#include <stdint.h>

#define BB 2
#define SEQ 2048
#define HID 2048
#define NH 16
#define HD 128
#define MROWS (BB*SEQ)   // 4096

// ---------------------------------------------------------------------------
// scratch (allocation-free rule: __device__ globals)
// ---------------------------------------------------------------------------
__device__ __nv_bfloat16 g_xhi[(size_t)MROWS * HID];
__device__ __nv_bfloat16 g_xlo[(size_t)MROWS * HID];
__device__ __nv_bfloat16 g_ahi[(size_t)MROWS * HID];
__device__ __nv_bfloat16 g_alo[(size_t)MROWS * HID];
__device__ __nv_bfloat16 g_whi[4][(size_t)HID * HID];
__device__ __nv_bfloat16 g_wlo[4][(size_t)HID * HID];

// per-head bf16 splits: [bh][s][d]
__device__ __nv_bfloat16 g_qh[(size_t)BB*NH*SEQ*HD];
__device__ __nv_bfloat16 g_ql[(size_t)BB*NH*SEQ*HD];
__device__ __nv_bfloat16 g_kh[(size_t)BB*NH*SEQ*HD];
__device__ __nv_bfloat16 g_kl[(size_t)BB*NH*SEQ*HD];
__device__ __nv_bfloat16 g_vh[(size_t)BB*NH*SEQ*HD];
__device__ __nv_bfloat16 g_vl[(size_t)BB*NH*SEQ*HD];

// rope table: [s][d] -> (cos, sin), d in [0,64)
__device__ float2 g_rt[(size_t)SEQ * 64];

__device__ __forceinline__ uint32_t smem_u32(const void* p) {
    uint32_t a;
    asm("{ .reg .u64 t; cvta.to.shared.u64 t, %1; cvt.u32.u64 %0, t; }"
        : "=r"(a) : "l"(p));
    return a;
}

#define CP16(sm, gp) \
    asm volatile("cp.async.cg.shared.global [%0], [%1], 16;" \
                 :: "r"(sm), "l"(gp) : "memory")
#define CP_COMMIT() asm volatile("cp.async.commit_group;" ::: "memory")
#define CP_WAIT2()  asm volatile("cp.async.wait_group 2;" ::: "memory")
#define CP_WAIT1()  asm volatile("cp.async.wait_group 1;" ::: "memory")
#define CP_WAIT0()  asm volatile("cp.async.wait_group 0;" ::: "memory")

#define LDSM4(r0,r1,r2,r3, addr) \
    asm volatile("ldmatrix.sync.aligned.m8n8.x4.shared.b16 {%0,%1,%2,%3}, [%4];" \
                 : "=r"(r0),"=r"(r1),"=r"(r2),"=r"(r3) : "r"(addr))
#define LDSM4T(r0,r1,r2,r3, addr) \
    asm volatile("ldmatrix.sync.aligned.m8n8.x4.trans.shared.b16 {%0,%1,%2,%3}, [%4];" \
                 : "=r"(r0),"=r"(r1),"=r"(r2),"=r"(r3) : "r"(addr))
#define LDSM2(r0,r1, addr) \
    asm volatile("ldmatrix.sync.aligned.m8n8.x2.shared.b16 {%0,%1}, [%2];" \
                 : "=r"(r0),"=r"(r1) : "r"(addr))

#define MMA16816(c, a, b) \
    asm volatile("mma.sync.aligned.m16n8k16.row.col.f32.bf16.bf16.f32 " \
                 "{%0,%1,%2,%3},{%4,%5,%6,%7},{%8,%9},{%0,%1,%2,%3};" \
                 : "+f"((c)[0]),"+f"((c)[1]),"+f"((c)[2]),"+f"((c)[3]) \
                 : "r"((a)[0]),"r"((a)[1]),"r"((a)[2]),"r"((a)[3]), \
                   "r"((b)[0]),"r"((b)[1]))

#define MMA_B2(c, a, b0v, b1v) \
    asm volatile("mma.sync.aligned.m16n8k16.row.col.f32.bf16.bf16.f32 " \
                 "{%0,%1,%2,%3},{%4,%5,%6,%7},{%8,%9},{%0,%1,%2,%3};" \
                 : "+f"((c)[0]),"+f"((c)[1]),"+f"((c)[2]),"+f"((c)[3]) \
                 : "r"((a)[0]),"r"((a)[1]),"r"((a)[2]),"r"((a)[3]), \
                   "r"(b0v),"r"(b1v))

__device__ __forceinline__ void split2(float x0, float x1,
                                       uint32_t& hi, uint32_t& lo) {
    __nv_bfloat16 h0 = __float2bfloat16(x0), h1 = __float2bfloat16(x1);
    __nv_bfloat16 l0 = __float2bfloat16(x0 - __bfloat162float(h0));
    __nv_bfloat16 l1 = __float2bfloat16(x1 - __bfloat162float(h1));
    hi = (uint32_t)__bfloat16_as_ushort(h0) |
         ((uint32_t)__bfloat16_as_ushort(h1) << 16);
    lo = (uint32_t)__bfloat16_as_ushort(l0) |
         ((uint32_t)__bfloat16_as_ushort(l1) << 16);
}

// ---------------------------------------------------------------------------
// fp32 -> bf16 hi/lo split (input x)
// ---------------------------------------------------------------------------
__global__ void split_kernel(const float* __restrict__ s,
                             __nv_bfloat16* __restrict__ hi,
                             __nv_bfloat16* __restrict__ lo, int n4)
{
    int i = blockIdx.x * blockDim.x + threadIdx.x;
    if (i >= n4) return;
    float4 x = ((const float4*)s)[i];
    uint32_t h0, l0, h1, l1;
    split2(x.x, x.y, h0, l0);
    split2(x.z, x.w, h1, l1);
    ((uint2*)hi)[i] = make_uint2(h0, h1);
    ((uint2*)lo)[i] = make_uint2(l0, l1);
}

// batched weight split: blockIdx.z selects among 4 weights
__global__ void split_w(const float* __restrict__ W0, const float* __restrict__ W1,
                        const float* __restrict__ W2, const float* __restrict__ W3,
                        int n4)
{
    int i = blockIdx.x * blockDim.x + threadIdx.x;
    if (i >= n4) return;
    int z = blockIdx.z;
    const float* W = (z == 0) ? W0 : (z == 1) ? W1 : (z == 2) ? W2 : W3;
    float4 x = ((const float4*)W)[i];
    uint32_t h0, l0, h1, l1;
    split2(x.x, x.y, h0, l0);
    split2(x.z, x.w, h1, l1);
    ((uint2*)g_whi[z])[i] = make_uint2(h0, h1);
    ((uint2*)g_wlo[z])[i] = make_uint2(l0, l1);
}

// rope cos/sin table
__global__ void rope_table()
{
    int idx = blockIdx.x * blockDim.x + threadIdx.x;  // SEQ*64
    int s = idx >> 6, d = idx & 63;
    float inv = expf(-logf(10000.f) * (float)d * (1.f / 64.f));
    float ang = (float)s * inv;
    g_rt[idx] = make_float2(cosf(ang), sinf(ang));
}

// ---------------------------------------------------------------------------
// bf16x3 mma.sync GEMM (NT): 2-stage cp.async, 2 CTAs/SM
// MODE 0: QKV fused epilogue (z = 0/1/2 -> Q/K/V, rope+scale+split to per-head)
// MODE 1: plain fp32 epilogue to outp (O projection, weight index 3)
// ---------------------------------------------------------------------------
#define GKC   32
#define GNIT  (HID / GKC)     // 64
#define ROWB  80
#define TILEB (128 * ROWB)    // 10240
#define STAGEB (4 * TILEB)    // 40960
#define GSMEM (2 * STAGEB)    // 81920

__device__ __forceinline__ void g_load_stage(
    uint32_t sb, const char* A0, const char* A1,
    const char* W0, const char* W1, int tid)
{
#pragma unroll
    for (int p = 0; p < 2; p++) {
        int q = tid + 256 * p;
        int row = q >> 2;
        int c = q & 3;
        uint32_t so = sb + row * ROWB + c * 16;
        size_t go = (size_t)row * (HID * 2) + c * 16;
        CP16(so,             A0 + go);
        CP16(so + TILEB,     A1 + go);
        CP16(so + 2 * TILEB, W0 + go);
        CP16(so + 3 * TILEB, W1 + go);
    }
}

template<int MODE>
__global__ __launch_bounds__(256, 2) void gemm_mma(
    const __nv_bfloat16* __restrict__ Ahi,
    const __nv_bfloat16* __restrict__ Alo,
    float* __restrict__ outp)
{
    extern __shared__ char sm[];
    const uint32_t smb = smem_u32(sm);
    const int tid = threadIdx.x;
    const int wid = tid >> 5, l = tid & 31;
    const int bm = blockIdx.y * 128;
    const int bn = blockIdx.x * 128;
    const int z = blockIdx.z;
    const int wm = (wid >> 2) * 64;
    const int wn = (wid & 3) * 32;

    const __nv_bfloat16* Whi = (MODE == 0) ? g_whi[z] : g_whi[3];
    const __nv_bfloat16* Wlo = (MODE == 0) ? g_wlo[z] : g_wlo[3];

    const char* A0 = (const char*)(Ahi + (size_t)bm * HID);
    const char* A1 = (const char*)(Alo + (size_t)bm * HID);
    const char* W0 = (const char*)(Whi + (size_t)bn * HID);
    const char* W1 = (const char*)(Wlo + (size_t)bn * HID);

    float acc[4][4][4];
#pragma unroll
    for (int mt = 0; mt < 4; mt++)
#pragma unroll
        for (int nt = 0; nt < 4; nt++)
#pragma unroll
            for (int r = 0; r < 4; r++) acc[mt][nt][r] = 0.f;

    const uint32_t aoff = (uint32_t)((wm + (l & 15)) * ROWB + (l >> 4) * 16);
    const uint32_t boff = (uint32_t)(2 * TILEB + (wn + (l & 7)) * ROWB +
                                     ((l >> 3) & 1) * 16);

    g_load_stage(smb, A0, A1, W0, W1, tid);
    CP_COMMIT();

    for (int it = 0; it < GNIT; it++) {
        if (it + 1 < GNIT) {
            size_t ko = (size_t)(it + 1) * GKC * 2;
            g_load_stage(smb + ((it + 1) & 1) * STAGEB,
                         A0 + ko, A1 + ko, W0 + ko, W1 + ko, tid);
            CP_COMMIT();
            CP_WAIT1();
        } else {
            CP_WAIT0();
        }
        __syncthreads();

        const uint32_t st = smb + (it & 1) * STAGEB;
#pragma unroll
        for (int s = 0; s < 2; s++) {
            uint32_t bh[4][2], bl[4][2];
#pragma unroll
            for (int nt = 0; nt < 4; nt++) {
                uint32_t ba = st + boff + nt * 8 * ROWB + s * 32;
                LDSM2(bh[nt][0], bh[nt][1], ba);
                LDSM2(bl[nt][0], bl[nt][1], ba + TILEB);
            }
#pragma unroll
            for (int mt = 0; mt < 4; mt++) {
                uint32_t ah[4], al[4];
                uint32_t aa = st + aoff + mt * 16 * ROWB + s * 32;
                LDSM4(ah[0], ah[1], ah[2], ah[3], aa);
                LDSM4(al[0], al[1], al[2], al[3], aa + TILEB);
#pragma unroll
                for (int nt = 0; nt < 4; nt++) {
                    MMA16816(acc[mt][nt], ah, bh[nt]);
                    MMA16816(acc[mt][nt], ah, bl[nt]);
                    MMA16816(acc[mt][nt], al, bh[nt]);
                }
            }
        }
        __syncthreads();
    }

    if (MODE == 1) {
        const int r0 = bm + wm + (l >> 2);
        const int c0 = bn + wn + (l & 3) * 2;
#pragma unroll
        for (int mt = 0; mt < 4; mt++)
#pragma unroll
            for (int nt = 0; nt < 4; nt++) {
                float* p0 = outp + (size_t)(r0 + mt * 16) * HID + c0 + nt * 8;
                *(float2*)p0 = make_float2(acc[mt][nt][0], acc[mt][nt][1]);
                float* p1 = p0 + 8 * HID;
                *(float2*)p1 = make_float2(acc[mt][nt][2], acc[mt][nt][3]);
            }
    } else {
        // fused epilogue: stage fp32 tile in smem, rope+scale+split, store bf16
        float* ft = (float*)sm;
#pragma unroll
        for (int mt = 0; mt < 4; mt++)
#pragma unroll
            for (int nt = 0; nt < 4; nt++) {
                int rr = wm + mt * 16 + (l >> 2);
                int cc = wn + nt * 8 + (l & 3) * 2;
                ft[rr * 132 + cc]           = acc[mt][nt][0];
                ft[rr * 132 + cc + 1]       = acc[mt][nt][1];
                ft[(rr + 8) * 132 + cc]     = acc[mt][nt][2];
                ft[(rr + 8) * 132 + cc + 1] = acc[mt][nt][3];
            }
        __syncthreads();

        __nv_bfloat16* DH = (z == 0) ? g_qh : (z == 1) ? g_kh : g_vh;
        __nv_bfloat16* DL = (z == 0) ? g_ql : (z == 1) ? g_kl : g_vl;
        const float scale = (z == 0) ? 0.08838834764831844f : 1.f;
        const int h = blockIdx.x;
#pragma unroll
        for (int jj = 0; jj < 16; jj++) {
            int idx = jj * 256 + tid;
            int r = idx >> 5, j = idx & 31, d0 = 2 * j;
            int gm = bm + r;
            int b = gm >> 11, s = gm & 2047;
            size_t dst = ((size_t)(b * NH + h) * SEQ + s) * HD;
            float a0 = ft[r * 132 + d0],      a1 = ft[r * 132 + d0 + 1];
            float e0 = ft[r * 132 + d0 + 64], e1 = ft[r * 132 + d0 + 65];
            float r0, r1, u0, u1;
            if (z < 2) {
                float2 cs0 = g_rt[s * 64 + d0];
                float2 cs1 = g_rt[s * 64 + d0 + 1];
                r0 = (a0 * cs0.x - e0 * cs0.y) * scale;
                r1 = (a1 * cs1.x - e1 * cs1.y) * scale;
                u0 = (e0 * cs0.x + a0 * cs0.y) * scale;
                u1 = (e1 * cs1.x + a1 * cs1.y) * scale;
            } else {
                r0 = a0; r1 = a1; u0 = e0; u1 = e1;
            }
            uint32_t hi, lo;
            split2(r0, r1, hi, lo);
            *(uint32_t*)&DH[dst + d0] = hi;
            *(uint32_t*)&DL[dst + d0] = lo;
            split2(u0, u1, hi, lo);
            *(uint32_t*)&DH[dst + d0 + 64] = hi;
            *(uint32_t*)&DL[dst + d0 + 64] = lo;
        }
    }
}

// ---------------------------------------------------------------------------
// Flash attention via mma.sync bf16x3
// Q fragments in registers; 3-stage cp.async KV pipeline
// ---------------------------------------------------------------------------
#define ACH 64
#define NCH (SEQ / ACH)       // 32
#define RB  272
#define STSZ   69632          // one stage: K hi/lo + V hi/lo
#define ATT_SM (3 * STSZ)     // 208896

__device__ __forceinline__ void att_load_kv(
    uint32_t stbase, const char* KH, const char* KL,
    const char* VH, const char* VL, int ck, int tid)
{
#pragma unroll
    for (int p = 0; p < 4; p++) {
        int idx = tid + 256 * p;
        int row = idx >> 4;
        int c = idx & 15;
        uint32_t off = row * RB + c * 16;
        size_t g = (size_t)(ck * 64 + row) * 256 + c * 16;
        CP16(stbase + off,         KH + g);
        CP16(stbase + 17408 + off, KL + g);
        CP16(stbase + 34816 + off, VH + g);
        CP16(stbase + 52224 + off, VL + g);
    }
}

__global__ __launch_bounds__(256) void attn_mma()
{
    extern __shared__ char sm[];
    const uint32_t smb = smem_u32(sm);
    const int tid = threadIdx.x;
    const int w = tid >> 5, l = tid & 31;
    const int qt = blockIdx.x;
    const int bh = blockIdx.y;
    const int b = bh >> 4, h = bh & 15;

    const char* QHg = (const char*)(g_qh + ((size_t)bh * SEQ + qt * 128) * HD);
    const char* QLg = (const char*)(g_ql + ((size_t)bh * SEQ + qt * 128) * HD);
    const char* KHg = (const char*)(g_kh + (size_t)bh * SEQ * HD);
    const char* KLg = (const char*)(g_kl + (size_t)bh * SEQ * HD);
    const char* VHg = (const char*)(g_vh + (size_t)bh * SEQ * HD);
    const char* VLg = (const char*)(g_vl + (size_t)bh * SEQ * HD);

    // stage Q into stage-0 smem, then hoist fragments to registers
#pragma unroll
    for (int p = 0; p < 8; p++) {
        int idx = tid + 256 * p;
        int row = idx >> 4;
        int c = idx & 15;
        uint32_t off = row * RB + c * 16;
        size_t g = (size_t)row * 256 + c * 16;
        CP16(smb + off,         QHg + g);
        CP16(smb + 34816 + off, QLg + g);
    }
    CP_COMMIT();
    CP_WAIT0();
    __syncthreads();

    uint32_t qh_r[8][4], ql_r[8][4];
    const uint32_t qa = smb + (w * 16 + (l & 15)) * RB + (l >> 4) * 16;
#pragma unroll
    for (int kc = 0; kc < 8; kc++) {
        LDSM4(qh_r[kc][0], qh_r[kc][1], qh_r[kc][2], qh_r[kc][3], qa + kc * 32);
        LDSM4(ql_r[kc][0], ql_r[kc][1], ql_r[kc][2], ql_r[kc][3],
              qa + 34816 + kc * 32);
    }
    __syncthreads();

    att_load_kv(smb,        KHg, KLg, VHg, VLg, 0, tid);
    CP_COMMIT();
    att_load_kv(smb + STSZ, KHg, KLg, VHg, VLg, 1, tid);
    CP_COMMIT();

    float sacc[8][4], oacc[16][4];
    float m0 = -1e30f, m1 = -1e30f, l0 = 0.f, l1 = 0.f;
#pragma unroll
    for (int nt = 0; nt < 16; nt++)
#pragma unroll
        for (int r = 0; r < 4; r++) oacc[nt][r] = 0.f;

    const uint32_t krow = (l & 7) + ((l >> 4) & 1) * 8;
    const uint32_t kcol = ((l >> 3) & 1) * 16;
    const uint32_t vrow = (l & 7) + ((l >> 3) & 1) * 8;
    const uint32_t vcol = ((l >> 4) & 1) * 16;

    for (int it = 0; it < NCH; it++) {
        if (it + 2 < NCH) {
            att_load_kv(smb + ((it + 2) % 3) * STSZ,
                        KHg, KLg, VHg, VLg, it + 2, tid);
            CP_COMMIT();
        }
        int pend = NCH - 1 - it;
        if (pend >= 2) { CP_WAIT2(); }
        else if (pend == 1) { CP_WAIT1(); }
        else { CP_WAIT0(); }
        __syncthreads();

        const uint32_t st = smb + (it % 3) * STSZ;

        // ---- S = Q K^T (bf16x3), Q from registers ----
#pragma unroll
        for (int nt = 0; nt < 8; nt++)
#pragma unroll
            for (int r = 0; r < 4; r++) sacc[nt][r] = 0.f;

#pragma unroll
        for (int kc = 0; kc < 8; kc++) {
#pragma unroll
            for (int g = 0; g < 4; g++) {
                uint32_t ka = st + (g * 16 + krow) * RB + kc * 32 + kcol;
                uint32_t bh_[4], bl_[4];
                LDSM4(bh_[0], bh_[1], bh_[2], bh_[3], ka);
                LDSM4(bl_[0], bl_[1], bl_[2], bl_[3], ka + 17408);
                MMA_B2(sacc[2 * g],     qh_r[kc], bh_[0], bh_[1]);
                MMA_B2(sacc[2 * g + 1], qh_r[kc], bh_[2], bh_[3]);
                MMA_B2(sacc[2 * g],     qh_r[kc], bl_[0], bl_[1]);
                MMA_B2(sacc[2 * g + 1], qh_r[kc], bl_[2], bl_[3]);
                MMA_B2(sacc[2 * g],     ql_r[kc], bh_[0], bh_[1]);
                MMA_B2(sacc[2 * g + 1], ql_r[kc], bh_[2], bh_[3]);
            }
        }

        // ---- online softmax ----
        float mx0 = -1e30f, mx1 = -1e30f;
#pragma unroll
        for (int nt = 0; nt < 8; nt++) {
            mx0 = fmaxf(mx0, fmaxf(sacc[nt][0], sacc[nt][1]));
            mx1 = fmaxf(mx1, fmaxf(sacc[nt][2], sacc[nt][3]));
        }
        mx0 = fmaxf(mx0, __shfl_xor_sync(0xffffffffu, mx0, 1));
        mx0 = fmaxf(mx0, __shfl_xor_sync(0xffffffffu, mx0, 2));
        mx1 = fmaxf(mx1, __shfl_xor_sync(0xffffffffu, mx1, 1));
        mx1 = fmaxf(mx1, __shfl_xor_sync(0xffffffffu, mx1, 2));
        float mn0 = fmaxf(m0, mx0), mn1 = fmaxf(m1, mx1);
        float corr0 = __expf(m0 - mn0), corr1 = __expf(m1 - mn1);
        m0 = mn0; m1 = mn1;
        float rs0 = 0.f, rs1 = 0.f;
#pragma unroll
        for (int nt = 0; nt < 8; nt++) {
            sacc[nt][0] = __expf(sacc[nt][0] - mn0);
            sacc[nt][1] = __expf(sacc[nt][1] - mn0);
            sacc[nt][2] = __expf(sacc[nt][2] - mn1);
            sacc[nt][3] = __expf(sacc[nt][3] - mn1);
            rs0 += sacc[nt][0] + sacc[nt][1];
            rs1 += sacc[nt][2] + sacc[nt][3];
        }
        rs0 += __shfl_xor_sync(0xffffffffu, rs0, 1);
        rs0 += __shfl_xor_sync(0xffffffffu, rs0, 2);
        rs1 += __shfl_xor_sync(0xffffffffu, rs1, 1);
        rs1 += __shfl_xor_sync(0xffffffffu, rs1, 2);
        l0 = l0 * corr0 + rs0;
        l1 = l1 * corr1 + rs1;
#pragma unroll
        for (int nt = 0; nt < 16; nt++) {
            oacc[nt][0] *= corr0; oacc[nt][1] *= corr0;
            oacc[nt][2] *= corr1; oacc[nt][3] *= corr1;
        }

        // ---- O += P V (bf16x3) ----
#pragma unroll
        for (int t = 0; t < 4; t++) {
            uint32_t pah[4], pal[4];
            split2(sacc[2 * t][0],     sacc[2 * t][1],     pah[0], pal[0]);
            split2(sacc[2 * t][2],     sacc[2 * t][3],     pah[1], pal[1]);
            split2(sacc[2 * t + 1][0], sacc[2 * t + 1][1], pah[2], pal[2]);
            split2(sacc[2 * t + 1][2], sacc[2 * t + 1][3], pah[3], pal[3]);
#pragma unroll
            for (int n = 0; n < 8; n++) {
                uint32_t va = st + 34816 + (t * 16 + vrow) * RB + n * 32 + vcol;
                uint32_t bh_[4], bl_[4];
                LDSM4T(bh_[0], bh_[1], bh_[2], bh_[3], va);
                LDSM4T(bl_[0], bl_[1], bl_[2], bl_[3], va + 17408);
                MMA_B2(oacc[2 * n],     pah, bh_[0], bh_[1]);
                MMA_B2(oacc[2 * n + 1], pah, bh_[2], bh_[3]);
                MMA_B2(oacc[2 * n],     pah, bl_[0], bl_[1]);
                MMA_B2(oacc[2 * n + 1], pah, bl_[2], bl_[3]);
                MMA_B2(oacc[2 * n],     pal, bh_[0], bh_[1]);
                MMA_B2(oacc[2 * n + 1], pal, bh_[2], bh_[3]);
            }
        }
        __syncthreads();
    }

    // ---- epilogue: normalize, split, store bf16 hi/lo ----
    const float inv0 = 1.f / l0, inv1 = 1.f / l1;
    const int row = qt * 128 + w * 16 + (l >> 2);
    size_t o0 = ((size_t)(b * SEQ) + row) * HID + h * HD + (l & 3) * 2;
#pragma unroll
    for (int nt = 0; nt < 16; nt++) {
        uint32_t hi, lo;
        split2(oacc[nt][0] * inv0, oacc[nt][1] * inv0, hi, lo);
        *(uint32_t*)&g_ahi[o0 + nt * 8] = hi;
        *(uint32_t*)&g_alo[o0 + nt * 8] = lo;
        split2(oacc[nt][2] * inv1, oacc[nt][3] * inv1, hi, lo);
        *(uint32_t*)&g_ahi[o0 + 8 * HID + nt * 8] = hi;
        *(uint32_t*)&g_alo[o0 + 8 * HID + nt * 8] = lo;
    }
}

// ---------------------------------------------------------------------------
extern "C" void kernel_launch(void* const* d_in, const int* in_sizes, int n_in,
                              void* d_out, int out_size)
{
    const float* x  = (const float*)d_in[0];
    const float* Wq = (const float*)d_in[1];
    const float* Wk = (const float*)d_in[2];
    const float* Wv = (const float*)d_in[3];
    const float* Wo = (const float*)d_in[4];
    float* out = (float*)d_out;

    __nv_bfloat16 *xhi, *xlo, *ahi, *alo;
    cudaGetSymbolAddress((void**)&xhi, g_xhi);
    cudaGetSymbolAddress((void**)&xlo, g_xlo);
    cudaGetSymbolAddress((void**)&ahi, g_ahi);
    cudaGetSymbolAddress((void**)&alo, g_alo);

    const int n4x = (MROWS * HID) / 4;
    const int n4w = (HID * HID) / 4;

    cudaFuncSetAttribute(gemm_mma<0>,
                         cudaFuncAttributeMaxDynamicSharedMemorySize, GSMEM);
    cudaFuncSetAttribute(gemm_mma<1>,
                         cudaFuncAttributeMaxDynamicSharedMemorySize, GSMEM);
    cudaFuncSetAttribute(attn_mma,
                         cudaFuncAttributeMaxDynamicSharedMemorySize, ATT_SM);

    split_kernel<<<n4x / 256, 256>>>(x, xhi, xlo, n4x);
    split_w<<<dim3(n4w / 256, 1, 4), 256>>>(Wq, Wk, Wv, Wo, n4w);
    rope_table<<<(SEQ * 64) / 256, 256>>>();

    // fused QKV projection (rope + split in epilogue)
    gemm_mma<0><<<dim3(HID / 128, MROWS / 128, 3), 256, GSMEM>>>(xhi, xlo, nullptr);

    attn_mma<<<dim3(SEQ / 128, BB * NH), 256, ATT_SM>>>();

    // O projection
    gemm_mma<1><<<dim3(HID / 128, MROWS / 128, 1), 256, GSMEM>>>(ahi, alo, out);
}